// round 5
// baseline (speedup 1.0000x reference)
#include <cuda_runtime.h>
#include <cuda_bf16.h>

#define NN 10000
#define NE 640000
#define C 128
#define NH 8
#define HD 16
#define BD 32
#define NEG_SLOPE 0.01f

// ---------------- packed f32x2 helpers (FFMA2 — only reachable via PTX) ----
#define FMA_F32X2(d, a, b, c) \
    asm("fma.rn.f32x2 %0, %1, %2, %3;" : "=l"(d) : "l"(a), "l"(b), "l"(c))

__device__ __forceinline__ unsigned long long pack2(float lo, float hi) {
    unsigned long long r;
    asm("mov.b64 %0, {%1, %2};" : "=l"(r) : "f"(lo), "f"(hi));
    return r;
}
__device__ __forceinline__ void unpack2(unsigned long long v, float& lo, float& hi) {
    asm("mov.b64 {%0, %1}, %2;" : "=f"(lo), "=f"(hi) : "l"(v));
}

// ---------------- scratch (device globals; no allocation allowed) ----------
__device__ float g_Q[NN * C];
__device__ float g_K[NN * C];
__device__ float g_V[NN * C];
__device__ int   g_cnt[NN];
__device__ int   g_off[NN + 1];
__device__ int   g_cur[NN];
__device__ int   g_slot_edge[NE];
__device__ int   g_slot_src[NE];
__device__ int   g_slot_dst[NE];
__device__ float g_ex[NE * NH];

// ---------------- CSR build ------------------------------------------------
__global__ void k_zero_cnt() {
    int i = blockIdx.x * blockDim.x + threadIdx.x;
    if (i < NN) g_cnt[i] = 0;
}

__global__ void k_hist(const int* __restrict__ dst) {
    int i = blockIdx.x * blockDim.x + threadIdx.x;
    if (i < NE) atomicAdd(&g_cnt[dst[i]], 1);
}

__global__ void k_scan() {
    __shared__ int s[1024];
    __shared__ int carry;
    int tid = threadIdx.x;
    if (tid == 0) carry = 0;
    __syncthreads();
    for (int base = 0; base < NN; base += 1024) {
        int idx = base + tid;
        int v = (idx < NN) ? g_cnt[idx] : 0;
        s[tid] = v;
        __syncthreads();
        for (int of = 1; of < 1024; of <<= 1) {
            int t = (tid >= of) ? s[tid - of] : 0;
            __syncthreads();
            s[tid] += t;
            __syncthreads();
        }
        int excl = carry + s[tid] - v;
        if (idx < NN) { g_off[idx] = excl; g_cur[idx] = excl; }
        int total = s[1023];
        __syncthreads();
        if (tid == 0) carry += total;
        __syncthreads();
    }
    if (tid == 0) g_off[NN] = NE;
}

__global__ void k_fill(const int* __restrict__ src, const int* __restrict__ dst) {
    int i = blockIdx.x * blockDim.x + threadIdx.x;
    if (i < NE) {
        int d = dst[i];
        int pos = atomicAdd(&g_cur[d], 1);
        g_slot_edge[pos] = i;
        g_slot_src[pos]  = src[i];
        g_slot_dst[pos]  = d;
    }
}

// ---------------- node projection GEMM: Out[M,128] = A[M,128] @ W[128,128] -
__global__ __launch_bounds__(256) void k_gemm128(
        const float* __restrict__ A, const float* __restrict__ W,
        float* __restrict__ Out, int M) {
    __shared__ float sA[64][32];
    __shared__ __align__(16) float sW[32][C];
    int tid = threadIdx.x;
    int tx = tid & 31;       // column group (4 cols each)
    int ty = tid >> 5;       // row group (8 rows each)
    int row0 = blockIdx.x * 64;

    unsigned long long acc[8][2];
#pragma unroll
    for (int i = 0; i < 8; i++) { acc[i][0] = 0ull; acc[i][1] = 0ull; }

    for (int kt = 0; kt < C; kt += 32) {
        for (int i = tid; i < 64 * 32; i += 256) {
            int r = i >> 5, k = i & 31;
            sA[r][k] = (row0 + r < M) ? A[(row0 + r) * C + kt + k] : 0.0f;
        }
        for (int i = tid; i < 32 * C; i += 256) {
            int k = i >> 7, c = i & 127;
            sW[k][c] = W[(kt + k) * C + c];
        }
        __syncthreads();
#pragma unroll
        for (int kk = 0; kk < 32; kk++) {
            ulonglong2 b2 = *(const ulonglong2*)&sW[kk][tx * 4];
#pragma unroll
            for (int i = 0; i < 8; i++) {
                unsigned long long aa = pack2(sA[ty * 8 + i][kk], sA[ty * 8 + i][kk]);
                FMA_F32X2(acc[i][0], aa, b2.x, acc[i][0]);
                FMA_F32X2(acc[i][1], aa, b2.y, acc[i][1]);
            }
        }
        __syncthreads();
    }
#pragma unroll
    for (int i = 0; i < 8; i++) {
        int r = row0 + ty * 8 + i;
        if (r < M) {
            float4 o;
            unpack2(acc[i][0], o.x, o.y);
            unpack2(acc[i][1], o.z, o.w);
            *(float4*)&Out[r * C + tx * 4] = o;
        }
    }
}

// ---------------- edge pass: projection + logits + exp ---------------------
// warp per CSR slot, grid-stride over slots; lane owns 4 channels
__global__ __launch_bounds__(256, 6) void k_edge(
        const float* __restrict__ edge_attrs,
        const float* __restrict__ W_E,
        const float* __restrict__ att) {
    __shared__ __align__(16) float sWE[BD * C];   // 16KB
    __shared__ __align__(16) float sAtt[C];
    int tid = threadIdx.x;
    for (int i = tid; i < BD * C; i += 256) sWE[i] = W_E[i];
    if (tid < C) sAtt[tid] = att[tid];
    __syncthreads();

    int lane = tid & 31;
    int warp = tid >> 5;
    int stride = gridDim.x * 8;
    const ulonglong2* w2 = (const ulonglong2*)sWE;
    float4 a = ((const float4*)sAtt)[lane];

    for (int slot = blockIdx.x * 8 + warp; slot < NE; slot += stride) {
        int e   = g_slot_edge[slot];
        int src = g_slot_src[slot];
        int dst = g_slot_dst[slot];

        float ea = edge_attrs[(long long)e * BD + lane];   // lane < 32 == BD
        // prefetch gathers early (independent of b-loop)
        float4 q = ((const float4*)g_Q)[dst * 32 + lane];
        float4 k = ((const float4*)g_K)[src * 32 + lane];

        unsigned long long acc01 = 0ull, acc23 = 0ull;
#pragma unroll
        for (int b = 0; b < BD; b++) {
            float eb = __shfl_sync(0xffffffffu, ea, b);
            unsigned long long ebb = pack2(eb, eb);
            ulonglong2 w = w2[b * 32 + lane];
            FMA_F32X2(acc01, ebb, w.x, acc01);
            FMA_F32X2(acc23, ebb, w.y, acc23);
        }
        float ax, ay, az, aw;
        unpack2(acc01, ax, ay);
        unpack2(acc23, az, aw);

        float sx = ax + q.x + k.x;
        float sy = ay + q.y + k.y;
        float sz = az + q.z + k.z;
        float sw = aw + q.w + k.w;
        // leaky relu
        sx = (sx > 0.f) ? sx : NEG_SLOPE * sx;
        sy = (sy > 0.f) ? sy : NEG_SLOPE * sy;
        sz = (sz > 0.f) ? sz : NEG_SLOPE * sz;
        sw = (sw > 0.f) ? sw : NEG_SLOPE * sw;

        float p = sx * a.x + sy * a.y + sz * a.z + sw * a.w;
        p += __shfl_xor_sync(0xffffffffu, p, 1);
        p += __shfl_xor_sync(0xffffffffu, p, 2);
        // lanes 4h..4h+3 all hold logit for head h
        if ((lane & 3) == 0) {
            g_ex[(long long)slot * NH + (lane >> 2)] = __expf(p);
        }
    }
}

// ---------------- per-node softmax-normalize + weighted aggregate ----------
// block per node, 128 threads (thread = output channel)
__global__ __launch_bounds__(128) void k_node(float* __restrict__ out) {
    int v = blockIdx.x;
    int tid = threadIdx.x;
    int s0 = g_off[v];
    int s1 = g_off[v + 1];

    __shared__ float sden[NH];
    __shared__ float rden[NH];
    if (tid < NH) sden[tid] = 0.0f;
    __syncthreads();

    // per-head denominators
    float d = 0.0f;
    for (int j = s0 * NH + tid; j < s1 * NH; j += 128) d += g_ex[j];
    atomicAdd(&sden[tid & 7], d);
    __syncthreads();
    if (tid < NH) rden[tid] = (sden[tid] > 0.0f) ? (1.0f / sden[tid]) : 0.0f;
    __syncthreads();

    int h = tid >> 4;   // head of this channel
    float acc = 0.0f;
    int j = s0;
    // unroll-by-4 for MLP (4 independent V-row loads in flight)
    for (; j + 3 < s1; j += 4) {
        float w0 = g_ex[(long long)(j + 0) * NH + h];
        float w1 = g_ex[(long long)(j + 1) * NH + h];
        float w2 = g_ex[(long long)(j + 2) * NH + h];
        float w3 = g_ex[(long long)(j + 3) * NH + h];
        float v0 = g_V[g_slot_src[j + 0] * C + tid];
        float v1 = g_V[g_slot_src[j + 1] * C + tid];
        float v2 = g_V[g_slot_src[j + 2] * C + tid];
        float v3 = g_V[g_slot_src[j + 3] * C + tid];
        acc += w0 * v0 + w1 * v1 + w2 * v2 + w3 * v3;
    }
    for (; j < s1; j++) {
        float w = g_ex[(long long)j * NH + h];
        acc += w * g_V[g_slot_src[j] * C + tid];
    }
    out[v * C + tid] = acc * rden[h];
}

// ---------------- launch ---------------------------------------------------
extern "C" void kernel_launch(void* const* d_in, const int* in_sizes, int n_in,
                              void* d_out, int out_size) {
    const float* senders    = (const float*)d_in[0];
    const float* receivers  = (const float*)d_in[1];
    const int*   edge_idx   = (const int*)d_in[2];
    const float* edge_attrs = (const float*)d_in[3];
    const float* W_Q        = (const float*)d_in[4];
    const float* W_K        = (const float*)d_in[5];
    const float* W_V        = (const float*)d_in[6];
    const float* W_E        = (const float*)d_in[7];
    const float* att        = (const float*)d_in[8];
    float* out = (float*)d_out;

    const int* src = edge_idx;
    const int* dst = edge_idx + NE;

    float* dQ; cudaGetSymbolAddress((void**)&dQ, g_Q);
    float* dK; cudaGetSymbolAddress((void**)&dK, g_K);
    float* dV; cudaGetSymbolAddress((void**)&dV, g_V);

    // CSR build
    k_zero_cnt<<<(NN + 255) / 256, 256>>>();
    k_hist<<<(NE + 255) / 256, 256>>>(dst);
    k_scan<<<1, 1024>>>();
    k_fill<<<(NE + 255) / 256, 256>>>(src, dst);

    // node projections
    int gblocks = (NN + 63) / 64;
    k_gemm128<<<gblocks, 256>>>(receivers, W_Q, dQ, NN);
    k_gemm128<<<gblocks, 256>>>(senders,   W_K, dK, NN);
    k_gemm128<<<gblocks, 256>>>(senders,   W_V, dV, NN);

    // edge pass (warp per slot, grid-stride; W_E smem fill amortized)
    k_edge<<<1184, 256>>>(edge_attrs, W_E, att);

    // node aggregation
    k_node<<<NN, 128>>>(out);
}

// round 6
// speedup vs baseline: 1.1152x; 1.1152x over previous
#include <cuda_runtime.h>
#include <cuda_bf16.h>

#define NN 10000
#define NE 640000
#define C 128
#define NH 8
#define HD 16
#define BD 32
#define NEG_SLOPE 0.01f

// ---------------- packed f32x2 helpers (FFMA2 — only reachable via PTX) ----
#define FMA_F32X2(d, a, b, c) \
    asm("fma.rn.f32x2 %0, %1, %2, %3;" : "=l"(d) : "l"(a), "l"(b), "l"(c))
#define ADD_F32X2(d, a, b) \
    asm("add.rn.f32x2 %0, %1, %2;" : "=l"(d) : "l"(a), "l"(b))

__device__ __forceinline__ unsigned long long pack2(float lo, float hi) {
    unsigned long long r;
    asm("mov.b64 %0, {%1, %2};" : "=l"(r) : "f"(lo), "f"(hi));
    return r;
}
__device__ __forceinline__ void unpack2(unsigned long long v, float& lo, float& hi) {
    asm("mov.b64 {%0, %1}, %2;" : "=f"(lo), "=f"(hi) : "l"(v));
}

// ---------------- scratch (device globals; no allocation allowed) ----------
__device__ float g_Q[NN * C];
__device__ float g_K[NN * C];
__device__ float g_V[NN * C];
__device__ int   g_cnt[NN];
__device__ int   g_off[NN + 1];
__device__ int   g_cur[NN];
__device__ int4  g_slot[NE];          // {edge, src, dst, 0}
__device__ float g_ex[NE * NH];

// ---------------- CSR build ------------------------------------------------
__global__ void k_zero_cnt() {
    int i = blockIdx.x * blockDim.x + threadIdx.x;
    if (i < NN) g_cnt[i] = 0;
}

__global__ void k_hist(const int* __restrict__ dst) {
    int i = blockIdx.x * blockDim.x + threadIdx.x;
    if (i < NE) atomicAdd(&g_cnt[dst[i]], 1);
}

__global__ void k_scan() {
    __shared__ int warp_tot[32];
    __shared__ int carry_s;
    int tid = threadIdx.x, lane = tid & 31, wid = tid >> 5;
    if (tid == 0) carry_s = 0;
    __syncthreads();
    for (int base = 0; base < NN; base += 1024) {
        int idx = base + tid;
        int v = (idx < NN) ? g_cnt[idx] : 0;
        int x = v;
#pragma unroll
        for (int of = 1; of < 32; of <<= 1) {
            int t = __shfl_up_sync(0xffffffffu, x, of);
            if (lane >= of) x += t;
        }
        if (lane == 31) warp_tot[wid] = x;
        __syncthreads();
        if (wid == 0) {
            int w = warp_tot[lane];
#pragma unroll
            for (int of = 1; of < 32; of <<= 1) {
                int t = __shfl_up_sync(0xffffffffu, w, of);
                if (lane >= of) w += t;
            }
            warp_tot[lane] = w;
        }
        __syncthreads();
        int incl = x + ((wid > 0) ? warp_tot[wid - 1] : 0);
        int excl = carry_s + incl - v;
        if (idx < NN) { g_off[idx] = excl; g_cur[idx] = excl; }
        int tot = warp_tot[31];
        __syncthreads();
        if (tid == 0) carry_s += tot;
        __syncthreads();
    }
    if (threadIdx.x == 0) g_off[NN] = NE;
}

__global__ void k_fill(const int* __restrict__ src, const int* __restrict__ dst) {
    int i = blockIdx.x * blockDim.x + threadIdx.x;
    if (i < NE) {
        int d = dst[i];
        int s = src[i];
        int pos = atomicAdd(&g_cur[d], 1);
        g_slot[pos] = make_int4(i, s, d, 0);
    }
}

// ---------------- node projection GEMM: Out[M,128] = A[M,128] @ W[128,128] -
__global__ __launch_bounds__(256) void k_gemm128(
        const float* __restrict__ A, const float* __restrict__ W,
        float* __restrict__ Out, int M) {
    __shared__ __align__(16) float2 sA2[64][32];   // duplicated (v,v) -> 16KB
    __shared__ __align__(16) float  sW[32][C];     // 16KB
    int tid = threadIdx.x;
    int tx = tid & 31;       // column group (4 cols each)
    int ty = tid >> 5;       // row group (8 rows each)
    int row0 = blockIdx.x * 64;

    unsigned long long acc[8][2];
#pragma unroll
    for (int i = 0; i < 8; i++) { acc[i][0] = 0ull; acc[i][1] = 0ull; }

    for (int kt = 0; kt < C; kt += 32) {
        for (int i = tid; i < 64 * 32; i += 256) {
            int r = i >> 5, k = i & 31;
            float a = (row0 + r < M) ? A[(row0 + r) * C + kt + k] : 0.0f;
            sA2[r][k] = make_float2(a, a);
        }
        for (int i = tid; i < 32 * C; i += 256) {
            int k = i >> 7, c = i & 127;
            sW[k][c] = W[(kt + k) * C + c];
        }
        __syncthreads();
#pragma unroll
        for (int kk = 0; kk < 32; kk++) {
            ulonglong2 b2 = *(const ulonglong2*)&sW[kk][tx * 4];
#pragma unroll
            for (int i = 0; i < 8; i++) {
                unsigned long long aa = *(const unsigned long long*)&sA2[ty * 8 + i][kk];
                FMA_F32X2(acc[i][0], aa, b2.x, acc[i][0]);
                FMA_F32X2(acc[i][1], aa, b2.y, acc[i][1]);
            }
        }
        __syncthreads();
    }
#pragma unroll
    for (int i = 0; i < 8; i++) {
        int r = row0 + ty * 8 + i;
        if (r < M) {
            float4 o;
            unpack2(acc[i][0], o.x, o.y);
            unpack2(acc[i][1], o.z, o.w);
            *(float4*)&Out[r * C + tx * 4] = o;
        }
    }
}

// ---------------- edge pass: projection + logits + exp ---------------------
// One warp covers ALL 128 channels of an edge (lane owns 4 channels).
// W_E held in registers (64 f32x2 per lane); edge coeffs broadcast from
// smem pre-duplicated as float2(v,v) so LDS.64 feeds FFMA2 directly.
__global__ __launch_bounds__(128, 3) void k_edge(
        const float* __restrict__ edge_attrs,
        const float* __restrict__ W_E,
        const float* __restrict__ att) {
    __shared__ __align__(16) float2 sEA[4][16][BD];   // per-warp, 16 edges -> 16KB
    int tid  = threadIdx.x;
    int lane = tid & 31;
    int warp = tid >> 5;

    // per-lane attention coeffs (4 channels)
    float4 a = ((const float4*)att)[lane];

    // hoist W_E columns for this lane's 4 channels into registers
    unsigned long long wA[BD], wB[BD];
#pragma unroll
    for (int b = 0; b < BD; b++) {
        float4 w = ((const float4*)W_E)[b * 32 + lane];
        wA[b] = pack2(w.x, w.y);
        wB[b] = pack2(w.z, w.w);
    }

    int tile0  = (blockIdx.x * 4 + warp) * 16;
    int tstep  = gridDim.x * 4 * 16;

    for (int tile = tile0; tile < NE; tile += tstep) {
        // lanes 0..15 fetch slot records for this tile
        int4 s4 = make_int4(0, 0, 0, 0);
        if (lane < 16) s4 = g_slot[tile + lane];

        // stage edge_attrs rows, duplicated for f32x2 broadcast
#pragma unroll 1
        for (int i = 0; i < 16; i++) {
            int e = __shfl_sync(0xffffffffu, s4.x, i);
            float v = edge_attrs[(long long)e * BD + lane];
            sEA[warp][i][lane] = make_float2(v, v);
        }
        __syncwarp();

#pragma unroll 1
        for (int i = 0; i < 16; i++) {
            int src = __shfl_sync(0xffffffffu, s4.y, i);
            int dst = __shfl_sync(0xffffffffu, s4.z, i);
            float4 q = ((const float4*)g_Q)[dst * 32 + lane];
            float4 k = ((const float4*)g_K)[src * 32 + lane];

            unsigned long long accA0 = 0ull, accA1 = 0ull;
            unsigned long long accB0 = 0ull, accB1 = 0ull;
#pragma unroll
            for (int b = 0; b < BD; b += 2) {
                unsigned long long e0 = *(const unsigned long long*)&sEA[warp][i][b];
                unsigned long long e1 = *(const unsigned long long*)&sEA[warp][i][b + 1];
                FMA_F32X2(accA0, e0, wA[b],     accA0);
                FMA_F32X2(accB0, e0, wB[b],     accB0);
                FMA_F32X2(accA1, e1, wA[b + 1], accA1);
                FMA_F32X2(accB1, e1, wB[b + 1], accB1);
            }
            ADD_F32X2(accA0, accA0, accA1);
            ADD_F32X2(accB0, accB0, accB1);

            float ax, ay, az, aw;
            unpack2(accA0, ax, ay);
            unpack2(accB0, az, aw);

            float sx = ax + q.x + k.x;
            float sy = ay + q.y + k.y;
            float sz = az + q.z + k.z;
            float sw = aw + q.w + k.w;
            // leaky relu
            sx = fmaxf(sx, 0.f) + NEG_SLOPE * fminf(sx, 0.f);
            sy = fmaxf(sy, 0.f) + NEG_SLOPE * fminf(sy, 0.f);
            sz = fmaxf(sz, 0.f) + NEG_SLOPE * fminf(sz, 0.f);
            sw = fmaxf(sw, 0.f) + NEG_SLOPE * fminf(sw, 0.f);

            float p = sx * a.x + sy * a.y + sz * a.z + sw * a.w;
            p += __shfl_xor_sync(0xffffffffu, p, 1);
            p += __shfl_xor_sync(0xffffffffu, p, 2);
            if ((lane & 3) == 0) {
                g_ex[(long long)(tile + i) * NH + (lane >> 2)] = __expf(p);
            }
        }
        __syncwarp();
    }
}

// ---------------- per-node softmax-normalize + weighted aggregate ----------
// block per node, 128 threads (thread = output channel)
__global__ __launch_bounds__(128) void k_node(float* __restrict__ out) {
    int v = blockIdx.x;
    int tid = threadIdx.x;
    int s0 = g_off[v];
    int s1 = g_off[v + 1];

    __shared__ float sden[NH];
    __shared__ float rden[NH];
    if (tid < NH) sden[tid] = 0.0f;
    __syncthreads();

    // per-head denominators
    float d = 0.0f;
    for (int j = s0 * NH + tid; j < s1 * NH; j += 128) d += g_ex[j];
    atomicAdd(&sden[tid & 7], d);
    __syncthreads();
    if (tid < NH) rden[tid] = (sden[tid] > 0.0f) ? (1.0f / sden[tid]) : 0.0f;
    __syncthreads();

    int h = tid >> 4;   // head of this channel
    float acc = 0.0f;
    int j = s0;
    // unroll-by-4 for MLP (4 independent V-row loads in flight)
    for (; j + 3 < s1; j += 4) {
        float w0 = g_ex[(long long)(j + 0) * NH + h];
        float w1 = g_ex[(long long)(j + 1) * NH + h];
        float w2 = g_ex[(long long)(j + 2) * NH + h];
        float w3 = g_ex[(long long)(j + 3) * NH + h];
        float v0 = g_V[g_slot[j + 0].y * C + tid];
        float v1 = g_V[g_slot[j + 1].y * C + tid];
        float v2 = g_V[g_slot[j + 2].y * C + tid];
        float v3 = g_V[g_slot[j + 3].y * C + tid];
        acc += w0 * v0 + w1 * v1 + w2 * v2 + w3 * v3;
    }
    for (; j < s1; j++) {
        float w = g_ex[(long long)j * NH + h];
        acc += w * g_V[g_slot[j].y * C + tid];
    }
    out[v * C + tid] = acc * rden[h];
}

// ---------------- launch ---------------------------------------------------
extern "C" void kernel_launch(void* const* d_in, const int* in_sizes, int n_in,
                              void* d_out, int out_size) {
    const float* senders    = (const float*)d_in[0];
    const float* receivers  = (const float*)d_in[1];
    const int*   edge_idx   = (const int*)d_in[2];
    const float* edge_attrs = (const float*)d_in[3];
    const float* W_Q        = (const float*)d_in[4];
    const float* W_K        = (const float*)d_in[5];
    const float* W_V        = (const float*)d_in[6];
    const float* W_E        = (const float*)d_in[7];
    const float* att        = (const float*)d_in[8];
    float* out = (float*)d_out;

    const int* src = edge_idx;
    const int* dst = edge_idx + NE;

    float* dQ; cudaGetSymbolAddress((void**)&dQ, g_Q);
    float* dK; cudaGetSymbolAddress((void**)&dK, g_K);
    float* dV; cudaGetSymbolAddress((void**)&dV, g_V);

    // CSR build
    k_zero_cnt<<<(NN + 255) / 256, 256>>>();
    k_hist<<<(NE + 255) / 256, 256>>>(dst);
    k_scan<<<1, 1024>>>();
    k_fill<<<(NE + 255) / 256, 256>>>(src, dst);

    // node projections
    int gblocks = (NN + 63) / 64;
    k_gemm128<<<gblocks, 256>>>(receivers, W_Q, dQ, NN);
    k_gemm128<<<gblocks, 256>>>(senders,   W_K, dK, NN);
    k_gemm128<<<gblocks, 256>>>(senders,   W_V, dV, NN);

    // edge pass: warp covers all 128 channels; W_E register-resident
    k_edge<<<444, 128>>>(edge_attrs, W_E, att);

    // node aggregation
    k_node<<<NN, 128>>>(out);
}

// round 8
// speedup vs baseline: 1.1712x; 1.0501x over previous
#include <cuda_runtime.h>
#include <cuda_bf16.h>

#define NN 10000
#define NE 640000
#define C 128
#define NH 8
#define HD 16
#define BD 32
#define NEG_SLOPE 0.01f

// ---------------- packed f32x2 helpers (FFMA2 — only reachable via PTX) ----
#define FMA_F32X2(d, a, b, c) \
    asm("fma.rn.f32x2 %0, %1, %2, %3;" : "=l"(d) : "l"(a), "l"(b), "l"(c))
#define ADD_F32X2(d, a, b) \
    asm("add.rn.f32x2 %0, %1, %2;" : "=l"(d) : "l"(a), "l"(b))

__device__ __forceinline__ unsigned long long pack2(float lo, float hi) {
    unsigned long long r;
    asm("mov.b64 %0, {%1, %2};" : "=l"(r) : "f"(lo), "f"(hi));
    return r;
}
__device__ __forceinline__ void unpack2(unsigned long long v, float& lo, float& hi) {
    asm("mov.b64 {%0, %1}, %2;" : "=f"(lo), "=f"(hi) : "l"(v));
}

// ---------------- scratch (device globals; no allocation allowed) ----------
__device__ float g_Q[NN * C];
__device__ float g_K[NN * C];
__device__ float g_V[NN * C];
__device__ int   g_cnt[NN];
__device__ int   g_off[NN + 1];
__device__ int   g_cur[NN];
__device__ int4  g_slot[NE];          // {edge, src, dst, 0}
__device__ float g_ex[NE * NH];

// ---------------- CSR build ------------------------------------------------
__global__ void k_zero_cnt() {
    int i = blockIdx.x * blockDim.x + threadIdx.x;
    if (i < NN) g_cnt[i] = 0;
}

__global__ void k_hist(const int* __restrict__ dst) {
    int i = blockIdx.x * blockDim.x + threadIdx.x;
    if (i < NE) atomicAdd(&g_cnt[dst[i]], 1);
}

__global__ void k_scan() {
    __shared__ int warp_tot[32];
    __shared__ int carry_s;
    int tid = threadIdx.x, lane = tid & 31, wid = tid >> 5;
    if (tid == 0) carry_s = 0;
    __syncthreads();
    for (int base = 0; base < NN; base += 1024) {
        int idx = base + tid;
        int v = (idx < NN) ? g_cnt[idx] : 0;
        int x = v;
#pragma unroll
        for (int of = 1; of < 32; of <<= 1) {
            int t = __shfl_up_sync(0xffffffffu, x, of);
            if (lane >= of) x += t;
        }
        if (lane == 31) warp_tot[wid] = x;
        __syncthreads();
        if (wid == 0) {
            int w = warp_tot[lane];
#pragma unroll
            for (int of = 1; of < 32; of <<= 1) {
                int t = __shfl_up_sync(0xffffffffu, w, of);
                if (lane >= of) w += t;
            }
            warp_tot[lane] = w;
        }
        __syncthreads();
        int incl = x + ((wid > 0) ? warp_tot[wid - 1] : 0);
        int excl = carry_s + incl - v;
        if (idx < NN) { g_off[idx] = excl; g_cur[idx] = excl; }
        int tot = warp_tot[31];
        __syncthreads();
        if (tid == 0) carry_s += tot;
        __syncthreads();
    }
    if (threadIdx.x == 0) g_off[NN] = NE;
}

__global__ void k_fill(const int* __restrict__ src, const int* __restrict__ dst) {
    int i = blockIdx.x * blockDim.x + threadIdx.x;
    if (i < NE) {
        int d = dst[i];
        int s = src[i];
        int pos = atomicAdd(&g_cur[d], 1);
        g_slot[pos] = make_int4(i, s, d, 0);
    }
}

// ---------------- node projection GEMM: Out[M,128] = A[M,128] @ W[128,128] -
__global__ __launch_bounds__(256) void k_gemm128(
        const float* __restrict__ A, const float* __restrict__ W,
        float* __restrict__ Out, int M) {
    __shared__ __align__(16) float2 sA2[64][32];   // duplicated (v,v) -> 16KB
    __shared__ __align__(16) float  sW[32][C];     // 16KB
    int tid = threadIdx.x;
    int tx = tid & 31;       // column group (4 cols each)
    int ty = tid >> 5;       // row group (8 rows each)
    int row0 = blockIdx.x * 64;

    unsigned long long acc[8][2];
#pragma unroll
    for (int i = 0; i < 8; i++) { acc[i][0] = 0ull; acc[i][1] = 0ull; }

    for (int kt = 0; kt < C; kt += 32) {
        for (int i = tid; i < 64 * 32; i += 256) {
            int r = i >> 5, k = i & 31;
            float a = (row0 + r < M) ? A[(row0 + r) * C + kt + k] : 0.0f;
            sA2[r][k] = make_float2(a, a);
        }
        for (int i = tid; i < 32 * C; i += 256) {
            int k = i >> 7, c = i & 127;
            sW[k][c] = W[(kt + k) * C + c];
        }
        __syncthreads();
#pragma unroll
        for (int kk = 0; kk < 32; kk++) {
            ulonglong2 b2 = *(const ulonglong2*)&sW[kk][tx * 4];
#pragma unroll
            for (int i = 0; i < 8; i++) {
                unsigned long long aa = *(const unsigned long long*)&sA2[ty * 8 + i][kk];
                FMA_F32X2(acc[i][0], aa, b2.x, acc[i][0]);
                FMA_F32X2(acc[i][1], aa, b2.y, acc[i][1]);
            }
        }
        __syncthreads();
    }
#pragma unroll
    for (int i = 0; i < 8; i++) {
        int r = row0 + ty * 8 + i;
        if (r < M) {
            float4 o;
            unpack2(acc[i][0], o.x, o.y);
            unpack2(acc[i][1], o.z, o.w);
            *(float4*)&Out[r * C + tx * 4] = o;
        }
    }
}

// ---------------- edge pass: projection + logits + exp ---------------------
// One warp covers ALL 128 channels of an edge (lane owns 4 channels).
// W_E register-resident; edge coeffs broadcast from smem as float2(v,v);
// Q/K gathers software-pipelined one edge ahead.
// NOTE: no min-blocks clause — forcing 3 CTAs/SM spilled the weight array.
__global__ __launch_bounds__(128) void k_edge(
        const float* __restrict__ edge_attrs,
        const float* __restrict__ W_E,
        const float* __restrict__ att) {
    __shared__ __align__(16) float2 sEA[4][16][BD];   // per-warp, 16 edges -> 16KB
    int tid  = threadIdx.x;
    int lane = tid & 31;
    int warp = tid >> 5;

    // per-lane attention coeffs (4 channels)
    float4 a = ((const float4*)att)[lane];

    // hoist W_E columns for this lane's 4 channels into registers
    unsigned long long wA[BD], wB[BD];
#pragma unroll
    for (int b = 0; b < BD; b++) {
        float4 w = ((const float4*)W_E)[b * 32 + lane];
        wA[b] = pack2(w.x, w.y);
        wB[b] = pack2(w.z, w.w);
    }

    int tile0  = (blockIdx.x * 4 + warp) * 16;
    int tstep  = gridDim.x * 4 * 16;

    for (int tile = tile0; tile < NE; tile += tstep) {
        // lanes 0..15 fetch slot records for this tile
        int4 s4 = make_int4(0, 0, 0, 0);
        if (lane < 16) s4 = g_slot[tile + lane];

        // stage edge_attrs rows, duplicated for f32x2 broadcast (16 indep LDGs)
#pragma unroll
        for (int i = 0; i < 16; i++) {
            int e = __shfl_sync(0xffffffffu, s4.x, i);
            float v = edge_attrs[(long long)e * BD + lane];
            sEA[warp][i][lane] = make_float2(v, v);
        }
        __syncwarp();

        // prefetch edge 0 gathers
        int src0 = __shfl_sync(0xffffffffu, s4.y, 0);
        int dst0 = __shfl_sync(0xffffffffu, s4.z, 0);
        float4 q = ((const float4*)g_Q)[dst0 * 32 + lane];
        float4 k = ((const float4*)g_K)[src0 * 32 + lane];

#pragma unroll 1
        for (int i = 0; i < 16; i++) {
            // prefetch next edge's gathers before the FFMA chain
            float4 qn, kn;
            if (i < 15) {
                int srcn = __shfl_sync(0xffffffffu, s4.y, i + 1);
                int dstn = __shfl_sync(0xffffffffu, s4.z, i + 1);
                qn = ((const float4*)g_Q)[dstn * 32 + lane];
                kn = ((const float4*)g_K)[srcn * 32 + lane];
            }

            unsigned long long accA0 = 0ull, accA1 = 0ull;
            unsigned long long accB0 = 0ull, accB1 = 0ull;
#pragma unroll
            for (int b = 0; b < BD; b += 2) {
                unsigned long long e0 = *(const unsigned long long*)&sEA[warp][i][b];
                unsigned long long e1 = *(const unsigned long long*)&sEA[warp][i][b + 1];
                FMA_F32X2(accA0, e0, wA[b],     accA0);
                FMA_F32X2(accB0, e0, wB[b],     accB0);
                FMA_F32X2(accA1, e1, wA[b + 1], accA1);
                FMA_F32X2(accB1, e1, wB[b + 1], accB1);
            }
            ADD_F32X2(accA0, accA0, accA1);
            ADD_F32X2(accB0, accB0, accB1);

            float ax, ay, az, aw;
            unpack2(accA0, ax, ay);
            unpack2(accB0, az, aw);

            float sx = ax + q.x + k.x;
            float sy = ay + q.y + k.y;
            float sz = az + q.z + k.z;
            float sw = aw + q.w + k.w;
            // leaky relu
            sx = fmaxf(sx, 0.f) + NEG_SLOPE * fminf(sx, 0.f);
            sy = fmaxf(sy, 0.f) + NEG_SLOPE * fminf(sy, 0.f);
            sz = fmaxf(sz, 0.f) + NEG_SLOPE * fminf(sz, 0.f);
            sw = fmaxf(sw, 0.f) + NEG_SLOPE * fminf(sw, 0.f);

            float p = sx * a.x + sy * a.y + sz * a.z + sw * a.w;
            p += __shfl_xor_sync(0xffffffffu, p, 1);
            p += __shfl_xor_sync(0xffffffffu, p, 2);
            if ((lane & 3) == 0) {
                g_ex[(long long)(tile + i) * NH + (lane >> 2)] = __expf(p);
            }
            q = qn; k = kn;
        }
        __syncwarp();
    }
}

// ---------------- per-node softmax-normalize + weighted aggregate ----------
// block per node, 128 threads (thread = output channel).
// Slots + softmax weights staged cooperatively in smem per 64-edge chunk.
#define NCHUNK 64
__global__ __launch_bounds__(128) void k_node(float* __restrict__ out) {
    int v = blockIdx.x;
    int tid = threadIdx.x;
    int s0 = g_off[v];
    int s1 = g_off[v + 1];

    __shared__ int   sSrc[NCHUNK];
    __shared__ float sEx[NCHUNK * NH];
    __shared__ float sden[NH];
    __shared__ float rden[NH];
    if (tid < NH) sden[tid] = 0.0f;

    int h = tid >> 4;        // head of this output channel
    int hh = tid & 7;        // head this thread accumulates denominator for
    float d = 0.0f;
    float acc = 0.0f;

    for (int c = s0; c < s1; c += NCHUNK) {
        int n = min(NCHUNK, s1 - c);
        __syncthreads();
        if (tid < n) sSrc[tid] = g_slot[c + tid].y;
        for (int i = tid; i < n * NH; i += 128) sEx[i] = g_ex[(long long)c * NH + i];
        __syncthreads();

        // denominator partials (stride-128 over n*8 values; head = tid&7 fixed)
        for (int i = tid; i < n * NH; i += 128) d += sEx[i];

        // weighted V gather
        int j = 0;
        for (; j + 3 < n; j += 4) {
            float w0 = sEx[(j + 0) * NH + h];
            float w1 = sEx[(j + 1) * NH + h];
            float w2 = sEx[(j + 2) * NH + h];
            float w3 = sEx[(j + 3) * NH + h];
            float v0 = g_V[sSrc[j + 0] * C + tid];
            float v1 = g_V[sSrc[j + 1] * C + tid];
            float v2 = g_V[sSrc[j + 2] * C + tid];
            float v3 = g_V[sSrc[j + 3] * C + tid];
            acc += w0 * v0 + w1 * v1 + w2 * v2 + w3 * v3;
        }
        for (; j < n; j++) {
            acc += sEx[j * NH + h] * g_V[sSrc[j] * C + tid];
        }
    }

    atomicAdd(&sden[hh], d);
    __syncthreads();
    if (tid < NH) rden[tid] = (sden[tid] > 0.0f) ? (1.0f / sden[tid]) : 0.0f;
    __syncthreads();

    out[v * C + tid] = acc * rden[h];
}

// ---------------- launch ---------------------------------------------------
extern "C" void kernel_launch(void* const* d_in, const int* in_sizes, int n_in,
                              void* d_out, int out_size) {
    const float* senders    = (const float*)d_in[0];
    const float* receivers  = (const float*)d_in[1];
    const int*   edge_idx   = (const int*)d_in[2];
    const float* edge_attrs = (const float*)d_in[3];
    const float* W_Q        = (const float*)d_in[4];
    const float* W_K        = (const float*)d_in[5];
    const float* W_V        = (const float*)d_in[6];
    const float* W_E        = (const float*)d_in[7];
    const float* att        = (const float*)d_in[8];
    float* out = (float*)d_out;

    const int* src = edge_idx;
    const int* dst = edge_idx + NE;

    float* dQ; cudaGetSymbolAddress((void**)&dQ, g_Q);
    float* dK; cudaGetSymbolAddress((void**)&dK, g_K);
    float* dV; cudaGetSymbolAddress((void**)&dV, g_V);

    // CSR build
    k_zero_cnt<<<(NN + 255) / 256, 256>>>();
    k_hist<<<(NE + 255) / 256, 256>>>(dst);
    k_scan<<<1, 1024>>>();
    k_fill<<<(NE + 255) / 256, 256>>>(src, dst);

    // node projections
    int gblocks = (NN + 63) / 64;
    k_gemm128<<<gblocks, 256>>>(receivers, W_Q, dQ, NN);
    k_gemm128<<<gblocks, 256>>>(senders,   W_K, dK, NN);
    k_gemm128<<<gblocks, 256>>>(senders,   W_V, dV, NN);

    // edge pass: warp covers all 128 channels; W_E register-resident
    k_edge<<<444, 128>>>(edge_attrs, W_E, att);

    // node aggregation
    k_node<<<NN, 128>>>(out);
}

// round 9
// speedup vs baseline: 1.4273x; 1.2187x over previous
#include <cuda_runtime.h>
#include <cuda_bf16.h>

#define NN 10000
#define NE 640000
#define C 128
#define NH 8
#define HD 16
#define BD 32
#define NEG_SLOPE 0.01f

// ---------------- packed f32x2 helpers (FFMA2 — only reachable via PTX) ----
#define FMA_F32X2(d, a, b, c) \
    asm("fma.rn.f32x2 %0, %1, %2, %3;" : "=l"(d) : "l"(a), "l"(b), "l"(c))
#define ADD_F32X2(d, a, b) \
    asm("add.rn.f32x2 %0, %1, %2;" : "=l"(d) : "l"(a), "l"(b))

__device__ __forceinline__ unsigned long long pack2(float lo, float hi) {
    unsigned long long r;
    asm("mov.b64 %0, {%1, %2};" : "=l"(r) : "f"(lo), "f"(hi));
    return r;
}
__device__ __forceinline__ void unpack2(unsigned long long v, float& lo, float& hi) {
    asm("mov.b64 {%0, %1}, %2;" : "=f"(lo), "=f"(hi) : "l"(v));
}

// ---------------- scratch (device globals; no allocation allowed) ----------
__device__ float g_Q[NN * C];
__device__ float g_K[NN * C];
__device__ float g_V[NN * C];
__device__ int   g_cnt[NN];
__device__ int   g_off[NN + 1];
__device__ int   g_cur[NN];
__device__ int2  g_slot[NE];          // {edge, src}
__device__ float g_ex[NE * NH];       // indexed by RAW edge id

// ---------------- node projection GEMM: Out[M,128] = A[M,128] @ W[128,128] -
__global__ __launch_bounds__(256) void k_gemm128(
        const float* __restrict__ A, const float* __restrict__ W,
        float* __restrict__ Out, int M) {
    __shared__ __align__(16) float2 sA2[64][32];   // duplicated (v,v) -> 16KB
    __shared__ __align__(16) float  sW[32][C];     // 16KB
    int tid = threadIdx.x;
    int tx = tid & 31;       // column group (4 cols each)
    int ty = tid >> 5;       // row group (8 rows each)
    int row0 = blockIdx.x * 64;

    unsigned long long acc[8][2];
#pragma unroll
    for (int i = 0; i < 8; i++) { acc[i][0] = 0ull; acc[i][1] = 0ull; }

    for (int kt = 0; kt < C; kt += 32) {
        for (int i = tid; i < 64 * 32; i += 256) {
            int r = i >> 5, k = i & 31;
            float a = (row0 + r < M) ? A[(row0 + r) * C + kt + k] : 0.0f;
            sA2[r][k] = make_float2(a, a);
        }
        for (int i = tid; i < 32 * C; i += 256) {
            int k = i >> 7, c = i & 127;
            sW[k][c] = W[(kt + k) * C + c];
        }
        __syncthreads();
#pragma unroll
        for (int kk = 0; kk < 32; kk++) {
            ulonglong2 b2 = *(const ulonglong2*)&sW[kk][tx * 4];
#pragma unroll
            for (int i = 0; i < 8; i++) {
                unsigned long long aa = *(const unsigned long long*)&sA2[ty * 8 + i][kk];
                FMA_F32X2(acc[i][0], aa, b2.x, acc[i][0]);
                FMA_F32X2(acc[i][1], aa, b2.y, acc[i][1]);
            }
        }
        __syncthreads();
    }
#pragma unroll
    for (int i = 0; i < 8; i++) {
        int r = row0 + ty * 8 + i;
        if (r < M) {
            float4 o;
            unpack2(acc[i][0], o.x, o.y);
            unpack2(acc[i][1], o.z, o.w);
            *(float4*)&Out[r * C + tx * 4] = o;
        }
    }
}

// ---------------- edge pass: projection + logits + exp ---------------------
// RAW edge order (no CSR dependency): edge_attrs streamed sequentially,
// src/dst straight from edge_indices. One warp covers all 128 channels of
// an edge; W_E register-resident; edge coeffs broadcast from smem as
// float2(v,v); Q/K gathers software-pipelined one edge ahead.
__global__ __launch_bounds__(128) void k_edge(
        const float* __restrict__ edge_attrs,
        const int*   __restrict__ esrc,
        const int*   __restrict__ edst,
        const float* __restrict__ W_E,
        const float* __restrict__ att) {
    __shared__ __align__(16) float2 sEA[4][16][BD];   // per-warp, 16 edges -> 16KB
    int tid  = threadIdx.x;
    int lane = tid & 31;
    int warp = tid >> 5;

    // per-lane attention coeffs (4 channels)
    float4 a = ((const float4*)att)[lane];

    // hoist W_E columns for this lane's 4 channels into registers
    unsigned long long wA[BD], wB[BD];
#pragma unroll
    for (int b = 0; b < BD; b++) {
        float4 w = ((const float4*)W_E)[b * 32 + lane];
        wA[b] = pack2(w.x, w.y);
        wB[b] = pack2(w.z, w.w);
    }

    int tile0 = (blockIdx.x * 4 + warp) * 16;
    int tstep = gridDim.x * 4 * 16;

    for (int tile = tile0; tile < NE; tile += tstep) {   // NE % 16 == 0
        // lanes 0..15 fetch src/dst for 16 consecutive edges (coalesced)
        int sv = 0, dv = 0;
        if (lane < 16) { sv = esrc[tile + lane]; dv = edst[tile + lane]; }

        // stage edge_attrs rows (sequential!), duplicated for f32x2 broadcast
#pragma unroll
        for (int i = 0; i < 16; i++) {
            float v = edge_attrs[(long long)(tile + i) * BD + lane];
            sEA[warp][i][lane] = make_float2(v, v);
        }
        __syncwarp();

        // prefetch edge 0 gathers
        int src0 = __shfl_sync(0xffffffffu, sv, 0);
        int dst0 = __shfl_sync(0xffffffffu, dv, 0);
        float4 q = ((const float4*)g_Q)[dst0 * 32 + lane];
        float4 k = ((const float4*)g_K)[src0 * 32 + lane];

#pragma unroll 1
        for (int i = 0; i < 16; i++) {
            // prefetch next edge's gathers before the FFMA chain
            float4 qn, kn;
            if (i < 15) {
                int srcn = __shfl_sync(0xffffffffu, sv, i + 1);
                int dstn = __shfl_sync(0xffffffffu, dv, i + 1);
                qn = ((const float4*)g_Q)[dstn * 32 + lane];
                kn = ((const float4*)g_K)[srcn * 32 + lane];
            }

            unsigned long long accA0 = 0ull, accA1 = 0ull;
            unsigned long long accB0 = 0ull, accB1 = 0ull;
#pragma unroll
            for (int b = 0; b < BD; b += 2) {
                unsigned long long e0 = *(const unsigned long long*)&sEA[warp][i][b];
                unsigned long long e1 = *(const unsigned long long*)&sEA[warp][i][b + 1];
                FMA_F32X2(accA0, e0, wA[b],     accA0);
                FMA_F32X2(accB0, e0, wB[b],     accB0);
                FMA_F32X2(accA1, e1, wA[b + 1], accA1);
                FMA_F32X2(accB1, e1, wB[b + 1], accB1);
            }
            ADD_F32X2(accA0, accA0, accA1);
            ADD_F32X2(accB0, accB0, accB1);

            float ax, ay, az, aw;
            unpack2(accA0, ax, ay);
            unpack2(accB0, az, aw);

            float sx = ax + q.x + k.x;
            float sy = ay + q.y + k.y;
            float sz = az + q.z + k.z;
            float sw = aw + q.w + k.w;
            // leaky relu
            sx = fmaxf(sx, 0.f) + NEG_SLOPE * fminf(sx, 0.f);
            sy = fmaxf(sy, 0.f) + NEG_SLOPE * fminf(sy, 0.f);
            sz = fmaxf(sz, 0.f) + NEG_SLOPE * fminf(sz, 0.f);
            sw = fmaxf(sw, 0.f) + NEG_SLOPE * fminf(sw, 0.f);

            float p = sx * a.x + sy * a.y + sz * a.z + sw * a.w;
            p += __shfl_xor_sync(0xffffffffu, p, 1);
            p += __shfl_xor_sync(0xffffffffu, p, 2);
            if ((lane & 3) == 0) {
                g_ex[(long long)(tile + i) * NH + (lane >> 2)] = __expf(p);
            }
            q = qn; k = kn;
        }
        __syncwarp();
    }
}

// ---------------- CSR build ------------------------------------------------
__global__ void k_zero_cnt() {
    int i = blockIdx.x * blockDim.x + threadIdx.x;
    if (i < NN) g_cnt[i] = 0;
}

__global__ void k_hist(const int* __restrict__ dst) {
    int i = blockIdx.x * blockDim.x + threadIdx.x;
    if (i < NE) atomicAdd(&g_cnt[dst[i]], 1);
}

__global__ void k_scan() {
    __shared__ int warp_tot[32];
    __shared__ int carry_s;
    int tid = threadIdx.x, lane = tid & 31, wid = tid >> 5;
    if (tid == 0) carry_s = 0;
    __syncthreads();
    for (int base = 0; base < NN; base += 1024) {
        int idx = base + tid;
        int v = (idx < NN) ? g_cnt[idx] : 0;
        int x = v;
#pragma unroll
        for (int of = 1; of < 32; of <<= 1) {
            int t = __shfl_up_sync(0xffffffffu, x, of);
            if (lane >= of) x += t;
        }
        if (lane == 31) warp_tot[wid] = x;
        __syncthreads();
        if (wid == 0) {
            int w = warp_tot[lane];
#pragma unroll
            for (int of = 1; of < 32; of <<= 1) {
                int t = __shfl_up_sync(0xffffffffu, w, of);
                if (lane >= of) w += t;
            }
            warp_tot[lane] = w;
        }
        __syncthreads();
        int incl = x + ((wid > 0) ? warp_tot[wid - 1] : 0);
        int excl = carry_s + incl - v;
        if (idx < NN) { g_off[idx] = excl; g_cur[idx] = excl; }
        int tot = warp_tot[31];
        __syncthreads();
        if (tid == 0) carry_s += tot;
        __syncthreads();
    }
    if (threadIdx.x == 0) g_off[NN] = NE;
}

__global__ void k_fill(const int* __restrict__ src, const int* __restrict__ dst) {
    int i = blockIdx.x * blockDim.x + threadIdx.x;
    if (i < NE) {
        int d = dst[i];
        int s = src[i];
        int pos = atomicAdd(&g_cur[d], 1);
        g_slot[pos] = make_int2(i, s);
    }
}

// ---------------- per-node softmax-normalize + weighted aggregate ----------
// block per node, 128 threads (thread = output channel).
// Slots + softmax weights staged cooperatively in smem per 64-edge chunk.
#define NCHUNK 64
__global__ __launch_bounds__(128) void k_node(float* __restrict__ out) {
    int v = blockIdx.x;
    int tid = threadIdx.x;
    int s0 = g_off[v];
    int s1 = g_off[v + 1];

    __shared__ int2  sSlot[NCHUNK];
    __shared__ float sEx[NCHUNK * NH];
    __shared__ float sden[NH];
    __shared__ float rden[NH];
    if (tid < NH) sden[tid] = 0.0f;

    int h = tid >> 4;        // head of this output channel
    int hh = tid & 7;        // head this thread accumulates denominator for
    float d = 0.0f;
    float acc = 0.0f;

    for (int c = s0; c < s1; c += NCHUNK) {
        int n = min(NCHUNK, s1 - c);
        __syncthreads();
        if (tid < n) sSlot[tid] = g_slot[c + tid];
        __syncthreads();
        // gather ex rows (32B each) for staged edges
        for (int i = tid; i < n * NH; i += 128) {
            int jj = i >> 3;
            sEx[i] = g_ex[(long long)sSlot[jj].x * NH + (i & 7)];
        }
        __syncthreads();

        // denominator partials (head = tid&7 fixed across iterations)
        for (int i = tid; i < n * NH; i += 128) d += sEx[i];

        // weighted V gather
        int j = 0;
        for (; j + 3 < n; j += 4) {
            float w0 = sEx[(j + 0) * NH + h];
            float w1 = sEx[(j + 1) * NH + h];
            float w2 = sEx[(j + 2) * NH + h];
            float w3 = sEx[(j + 3) * NH + h];
            float v0 = g_V[sSlot[j + 0].y * C + tid];
            float v1 = g_V[sSlot[j + 1].y * C + tid];
            float v2 = g_V[sSlot[j + 2].y * C + tid];
            float v3 = g_V[sSlot[j + 3].y * C + tid];
            acc += w0 * v0 + w1 * v1 + w2 * v2 + w3 * v3;
        }
        for (; j < n; j++) {
            acc += sEx[j * NH + h] * g_V[sSlot[j].y * C + tid];
        }
    }

    atomicAdd(&sden[hh], d);
    __syncthreads();
    if (tid < NH) rden[tid] = (sden[tid] > 0.0f) ? (1.0f / sden[tid]) : 0.0f;
    __syncthreads();

    out[v * C + tid] = acc * rden[h];
}

// ---------------- launch ---------------------------------------------------
extern "C" void kernel_launch(void* const* d_in, const int* in_sizes, int n_in,
                              void* d_out, int out_size) {
    const float* senders    = (const float*)d_in[0];
    const float* receivers  = (const float*)d_in[1];
    const int*   edge_idx   = (const int*)d_in[2];
    const float* edge_attrs = (const float*)d_in[3];
    const float* W_Q        = (const float*)d_in[4];
    const float* W_K        = (const float*)d_in[5];
    const float* W_V        = (const float*)d_in[6];
    const float* W_E        = (const float*)d_in[7];
    const float* att        = (const float*)d_in[8];
    float* out = (float*)d_out;

    const int* src = edge_idx;
    const int* dst = edge_idx + NE;

    float* dQ; cudaGetSymbolAddress((void**)&dQ, g_Q);
    float* dK; cudaGetSymbolAddress((void**)&dK, g_K);
    float* dV; cudaGetSymbolAddress((void**)&dV, g_V);

    // node projections (1-3)
    int gblocks = (NN + 63) / 64;
    k_gemm128<<<gblocks, 256>>>(receivers, W_Q, dQ, NN);
    k_gemm128<<<gblocks, 256>>>(senders,   W_K, dK, NN);
    k_gemm128<<<gblocks, 256>>>(senders,   W_V, dV, NN);

    // edge pass (4th launch — profiled slot): raw edge order, no CSR dep
    k_edge<<<296, 128>>>(edge_attrs, src, dst, W_E, att);

    // CSR build (5-8)
    k_zero_cnt<<<(NN + 255) / 256, 256>>>();
    k_hist<<<(NE + 255) / 256, 256>>>(dst);
    k_scan<<<1, 1024>>>();
    k_fill<<<(NE + 255) / 256, 256>>>(src, dst);

    // node aggregation (9)
    k_node<<<NN, 128>>>(out);
}

// round 10
// speedup vs baseline: 1.5476x; 1.0843x over previous
#include <cuda_runtime.h>
#include <cuda_bf16.h>

#define NN 10000
#define NE 640000
#define C 128
#define NH 8
#define HD 16
#define BD 32
#define NEG_SLOPE 0.01f

// ---------------- packed f32x2 helpers (FFMA2 — only reachable via PTX) ----
#define FMA_F32X2(d, a, b, c) \
    asm("fma.rn.f32x2 %0, %1, %2, %3;" : "=l"(d) : "l"(a), "l"(b), "l"(c))
#define ADD_F32X2(d, a, b) \
    asm("add.rn.f32x2 %0, %1, %2;" : "=l"(d) : "l"(a), "l"(b))

__device__ __forceinline__ unsigned long long pack2(float lo, float hi) {
    unsigned long long r;
    asm("mov.b64 %0, {%1, %2};" : "=l"(r) : "f"(lo), "f"(hi));
    return r;
}
__device__ __forceinline__ void unpack2(unsigned long long v, float& lo, float& hi) {
    asm("mov.b64 {%0, %1}, %2;" : "=f"(lo), "=f"(hi) : "l"(v));
}

// ---------------- scratch (device globals; no allocation allowed) ----------
__device__ float g_Q[NN * C];
__device__ float g_K[NN * C];
__device__ float g_V[NN * C];
__device__ int   g_cnt[NN];
__device__ int   g_off[NN + 1];
__device__ int   g_cur[NN];
__device__ int2  g_slot[NE];          // {edge, src}
__device__ float g_ex[NE * NH];       // indexed by RAW edge id

// ---------------- node projection GEMM: Out[M,128] = A[M,128] @ W[128,128] -
__global__ __launch_bounds__(256) void k_gemm128(
        const float* __restrict__ A, const float* __restrict__ W,
        float* __restrict__ Out, int M) {
    __shared__ __align__(16) float2 sA2[64][32];   // duplicated (v,v) -> 16KB
    __shared__ __align__(16) float  sW[32][C];     // 16KB
    int tid = threadIdx.x;
    int tx = tid & 31;       // column group (4 cols each)
    int ty = tid >> 5;       // row group (8 rows each)
    int row0 = blockIdx.x * 64;

    unsigned long long acc[8][2];
#pragma unroll
    for (int i = 0; i < 8; i++) { acc[i][0] = 0ull; acc[i][1] = 0ull; }

    for (int kt = 0; kt < C; kt += 32) {
        for (int i = tid; i < 64 * 32; i += 256) {
            int r = i >> 5, k = i & 31;
            float a = (row0 + r < M) ? A[(row0 + r) * C + kt + k] : 0.0f;
            sA2[r][k] = make_float2(a, a);
        }
        for (int i = tid; i < 32 * C; i += 256) {
            int k = i >> 7, c = i & 127;
            sW[k][c] = W[(kt + k) * C + c];
        }
        __syncthreads();
#pragma unroll
        for (int kk = 0; kk < 32; kk++) {
            ulonglong2 b2 = *(const ulonglong2*)&sW[kk][tx * 4];
#pragma unroll
            for (int i = 0; i < 8; i++) {
                unsigned long long aa = *(const unsigned long long*)&sA2[ty * 8 + i][kk];
                FMA_F32X2(acc[i][0], aa, b2.x, acc[i][0]);
                FMA_F32X2(acc[i][1], aa, b2.y, acc[i][1]);
            }
        }
        __syncthreads();
    }
#pragma unroll
    for (int i = 0; i < 8; i++) {
        int r = row0 + ty * 8 + i;
        if (r < M) {
            float4 o;
            unpack2(acc[i][0], o.x, o.y);
            unpack2(acc[i][1], o.z, o.w);
            *(float4*)&Out[r * C + tx * 4] = o;
        }
    }
}

// ---------------- edge pass: projection + logits + exp ---------------------
// RAW edge order. One warp covers all 128 channels of an edge; W_E
// register-resident; edge coeffs broadcast from smem as float2(v,v).
// Edges processed in PAIRS with prefetch distance 2 (4 Q/K rows in flight,
// 8 independent FFMA2 chains) to cover the ~250-cyc L2 gather latency.
__global__ __launch_bounds__(128) void k_edge(
        const float* __restrict__ edge_attrs,
        const int*   __restrict__ esrc,
        const int*   __restrict__ edst,
        const float* __restrict__ W_E,
        const float* __restrict__ att) {
    __shared__ __align__(16) float2 sEA[4][16][BD];   // per-warp, 16 edges -> 16KB
    int tid  = threadIdx.x;
    int lane = tid & 31;
    int warp = tid >> 5;

    // per-lane attention coeffs (4 channels)
    float4 a = ((const float4*)att)[lane];

    // hoist W_E columns for this lane's 4 channels into registers
    unsigned long long wA[BD], wB[BD];
#pragma unroll
    for (int b = 0; b < BD; b++) {
        float4 w = ((const float4*)W_E)[b * 32 + lane];
        wA[b] = pack2(w.x, w.y);
        wB[b] = pack2(w.z, w.w);
    }

    int tile0 = (blockIdx.x * 4 + warp) * 16;
    int tstep = gridDim.x * 4 * 16;

    for (int tile = tile0; tile < NE; tile += tstep) {   // NE % 16 == 0
        // lanes 0..15 fetch src/dst for 16 consecutive edges (coalesced)
        int sv = 0, dv = 0;
        if (lane < 16) { sv = esrc[tile + lane]; dv = edst[tile + lane]; }

        // stage edge_attrs rows (sequential!), duplicated for f32x2 broadcast
#pragma unroll
        for (int i = 0; i < 16; i++) {
            float v = edge_attrs[(long long)(tile + i) * BD + lane];
            sEA[warp][i][lane] = make_float2(v, v);
        }
        __syncwarp();

        // prefetch pair 0 (edges 0,1)
        int s0i = __shfl_sync(0xffffffffu, sv, 0);
        int d0i = __shfl_sync(0xffffffffu, dv, 0);
        int s1i = __shfl_sync(0xffffffffu, sv, 1);
        int d1i = __shfl_sync(0xffffffffu, dv, 1);
        float4 qa = ((const float4*)g_Q)[d0i * 32 + lane];
        float4 ka = ((const float4*)g_K)[s0i * 32 + lane];
        float4 qb = ((const float4*)g_Q)[d1i * 32 + lane];
        float4 kb = ((const float4*)g_K)[s1i * 32 + lane];

#pragma unroll 1
        for (int i = 0; i < 16; i += 2) {
            // prefetch next pair before this pair's FFMA chains
            float4 qa2, ka2, qb2, kb2;
            if (i + 2 < 16) {
                int sn0 = __shfl_sync(0xffffffffu, sv, i + 2);
                int dn0 = __shfl_sync(0xffffffffu, dv, i + 2);
                int sn1 = __shfl_sync(0xffffffffu, sv, i + 3);
                int dn1 = __shfl_sync(0xffffffffu, dv, i + 3);
                qa2 = ((const float4*)g_Q)[dn0 * 32 + lane];
                ka2 = ((const float4*)g_K)[sn0 * 32 + lane];
                qb2 = ((const float4*)g_Q)[dn1 * 32 + lane];
                kb2 = ((const float4*)g_K)[sn1 * 32 + lane];
            }

            // edge i and i+1 interleaved: 8 independent FFMA2 chains
            unsigned long long aA0 = 0ull, aA1 = 0ull, aB0 = 0ull, aB1 = 0ull;
            unsigned long long bA0 = 0ull, bA1 = 0ull, bB0 = 0ull, bB1 = 0ull;
#pragma unroll
            for (int b = 0; b < BD; b += 2) {
                unsigned long long ea0 = *(const unsigned long long*)&sEA[warp][i][b];
                unsigned long long ea1 = *(const unsigned long long*)&sEA[warp][i][b + 1];
                unsigned long long eb0 = *(const unsigned long long*)&sEA[warp][i + 1][b];
                unsigned long long eb1 = *(const unsigned long long*)&sEA[warp][i + 1][b + 1];
                FMA_F32X2(aA0, ea0, wA[b],     aA0);
                FMA_F32X2(aB0, ea0, wB[b],     aB0);
                FMA_F32X2(bA0, eb0, wA[b],     bA0);
                FMA_F32X2(bB0, eb0, wB[b],     bB0);
                FMA_F32X2(aA1, ea1, wA[b + 1], aA1);
                FMA_F32X2(aB1, ea1, wB[b + 1], aB1);
                FMA_F32X2(bA1, eb1, wA[b + 1], bA1);
                FMA_F32X2(bB1, eb1, wB[b + 1], bB1);
            }
            ADD_F32X2(aA0, aA0, aA1);
            ADD_F32X2(aB0, aB0, aB1);
            ADD_F32X2(bA0, bA0, bA1);
            ADD_F32X2(bB0, bB0, bB1);

            // ---- edge i ----
            {
                float ax, ay, az, aw;
                unpack2(aA0, ax, ay);
                unpack2(aB0, az, aw);
                float sx = ax + qa.x + ka.x;
                float sy = ay + qa.y + ka.y;
                float sz = az + qa.z + ka.z;
                float sw = aw + qa.w + ka.w;
                sx = fmaxf(sx, 0.f) + NEG_SLOPE * fminf(sx, 0.f);
                sy = fmaxf(sy, 0.f) + NEG_SLOPE * fminf(sy, 0.f);
                sz = fmaxf(sz, 0.f) + NEG_SLOPE * fminf(sz, 0.f);
                sw = fmaxf(sw, 0.f) + NEG_SLOPE * fminf(sw, 0.f);
                float p = sx * a.x + sy * a.y + sz * a.z + sw * a.w;
                p += __shfl_xor_sync(0xffffffffu, p, 1);
                p += __shfl_xor_sync(0xffffffffu, p, 2);
                if ((lane & 3) == 0) {
                    g_ex[(long long)(tile + i) * NH + (lane >> 2)] = __expf(p);
                }
            }
            // ---- edge i+1 ----
            {
                float ax, ay, az, aw;
                unpack2(bA0, ax, ay);
                unpack2(bB0, az, aw);
                float sx = ax + qb.x + kb.x;
                float sy = ay + qb.y + kb.y;
                float sz = az + qb.z + kb.z;
                float sw = aw + qb.w + kb.w;
                sx = fmaxf(sx, 0.f) + NEG_SLOPE * fminf(sx, 0.f);
                sy = fmaxf(sy, 0.f) + NEG_SLOPE * fminf(sy, 0.f);
                sz = fmaxf(sz, 0.f) + NEG_SLOPE * fminf(sz, 0.f);
                sw = fmaxf(sw, 0.f) + NEG_SLOPE * fminf(sw, 0.f);
                float p = sx * a.x + sy * a.y + sz * a.z + sw * a.w;
                p += __shfl_xor_sync(0xffffffffu, p, 1);
                p += __shfl_xor_sync(0xffffffffu, p, 2);
                if ((lane & 3) == 0) {
                    g_ex[(long long)(tile + i + 1) * NH + (lane >> 2)] = __expf(p);
                }
            }
            qa = qa2; ka = ka2; qb = qb2; kb = kb2;
        }
        __syncwarp();
    }
}

// ---------------- CSR build ------------------------------------------------
__global__ void k_zero_cnt() {
    int i = blockIdx.x * blockDim.x + threadIdx.x;
    if (i < NN) g_cnt[i] = 0;
}

__global__ void k_hist(const int* __restrict__ dst) {
    int i = blockIdx.x * blockDim.x + threadIdx.x;
    if (i < NE) atomicAdd(&g_cnt[dst[i]], 1);
}

__global__ void k_scan() {
    __shared__ int warp_tot[32];
    __shared__ int carry_s;
    int tid = threadIdx.x, lane = tid & 31, wid = tid >> 5;
    if (tid == 0) carry_s = 0;
    __syncthreads();
    for (int base = 0; base < NN; base += 1024) {
        int idx = base + tid;
        int v = (idx < NN) ? g_cnt[idx] : 0;
        int x = v;
#pragma unroll
        for (int of = 1; of < 32; of <<= 1) {
            int t = __shfl_up_sync(0xffffffffu, x, of);
            if (lane >= of) x += t;
        }
        if (lane == 31) warp_tot[wid] = x;
        __syncthreads();
        if (wid == 0) {
            int w = warp_tot[lane];
#pragma unroll
            for (int of = 1; of < 32; of <<= 1) {
                int t = __shfl_up_sync(0xffffffffu, w, of);
                if (lane >= of) w += t;
            }
            warp_tot[lane] = w;
        }
        __syncthreads();
        int incl = x + ((wid > 0) ? warp_tot[wid - 1] : 0);
        int excl = carry_s + incl - v;
        if (idx < NN) { g_off[idx] = excl; g_cur[idx] = excl; }
        int tot = warp_tot[31];
        __syncthreads();
        if (tid == 0) carry_s += tot;
        __syncthreads();
    }
    if (threadIdx.x == 0) g_off[NN] = NE;
}

__global__ void k_fill(const int* __restrict__ src, const int* __restrict__ dst) {
    int i = blockIdx.x * blockDim.x + threadIdx.x;
    if (i < NE) {
        int d = dst[i];
        int s = src[i];
        int pos = atomicAdd(&g_cur[d], 1);
        g_slot[pos] = make_int2(i, s);
    }
}

// ---------------- per-node softmax-normalize + weighted aggregate ----------
// block per node, 128 threads (thread = output channel).
// Slots + softmax weights staged cooperatively in smem per 64-edge chunk.
#define NCHUNK 64
__global__ __launch_bounds__(128) void k_node(float* __restrict__ out) {
    int v = blockIdx.x;
    int tid = threadIdx.x;
    int s0 = g_off[v];
    int s1 = g_off[v + 1];

    __shared__ int2  sSlot[NCHUNK];
    __shared__ float sEx[NCHUNK * NH];
    __shared__ float sden[NH];
    __shared__ float rden[NH];
    if (tid < NH) sden[tid] = 0.0f;

    int h = tid >> 4;        // head of this output channel
    int hh = tid & 7;        // head this thread accumulates denominator for
    float d = 0.0f;
    float acc = 0.0f;

    for (int c = s0; c < s1; c += NCHUNK) {
        int n = min(NCHUNK, s1 - c);
        __syncthreads();
        if (tid < n) sSlot[tid] = g_slot[c + tid];
        __syncthreads();
        // gather ex rows (32B each) for staged edges
        for (int i = tid; i < n * NH; i += 128) {
            int jj = i >> 3;
            sEx[i] = g_ex[(long long)sSlot[jj].x * NH + (i & 7)];
        }
        __syncthreads();

        // denominator partials (head = tid&7 fixed across iterations)
        for (int i = tid; i < n * NH; i += 128) d += sEx[i];

        // weighted V gather
        int j = 0;
        for (; j + 3 < n; j += 4) {
            float w0 = sEx[(j + 0) * NH + h];
            float w1 = sEx[(j + 1) * NH + h];
            float w2 = sEx[(j + 2) * NH + h];
            float w3 = sEx[(j + 3) * NH + h];
            float v0 = g_V[sSlot[j + 0].y * C + tid];
            float v1 = g_V[sSlot[j + 1].y * C + tid];
            float v2 = g_V[sSlot[j + 2].y * C + tid];
            float v3 = g_V[sSlot[j + 3].y * C + tid];
            acc += w0 * v0 + w1 * v1 + w2 * v2 + w3 * v3;
        }
        for (; j < n; j++) {
            acc += sEx[j * NH + h] * g_V[sSlot[j].y * C + tid];
        }
    }

    atomicAdd(&sden[hh], d);
    __syncthreads();
    if (tid < NH) rden[tid] = (sden[tid] > 0.0f) ? (1.0f / sden[tid]) : 0.0f;
    __syncthreads();

    out[v * C + tid] = acc * rden[h];
}

// ---------------- launch ---------------------------------------------------
extern "C" void kernel_launch(void* const* d_in, const int* in_sizes, int n_in,
                              void* d_out, int out_size) {
    const float* senders    = (const float*)d_in[0];
    const float* receivers  = (const float*)d_in[1];
    const int*   edge_idx   = (const int*)d_in[2];
    const float* edge_attrs = (const float*)d_in[3];
    const float* W_Q        = (const float*)d_in[4];
    const float* W_K        = (const float*)d_in[5];
    const float* W_V        = (const float*)d_in[6];
    const float* W_E        = (const float*)d_in[7];
    const float* att        = (const float*)d_in[8];
    float* out = (float*)d_out;

    const int* src = edge_idx;
    const int* dst = edge_idx + NE;

    float* dQ; cudaGetSymbolAddress((void**)&dQ, g_Q);
    float* dK; cudaGetSymbolAddress((void**)&dK, g_K);
    float* dV; cudaGetSymbolAddress((void**)&dV, g_V);

    // node projections (1-3)
    int gblocks = (NN + 63) / 64;
    k_gemm128<<<gblocks, 256>>>(receivers, W_Q, dQ, NN);
    k_gemm128<<<gblocks, 256>>>(senders,   W_K, dK, NN);
    k_gemm128<<<gblocks, 256>>>(senders,   W_V, dV, NN);

    // edge pass (4th launch — profiled slot): raw edge order, no CSR dep
    k_edge<<<296, 128>>>(edge_attrs, src, dst, W_E, att);

    // CSR build (5-8)
    k_zero_cnt<<<(NN + 255) / 256, 256>>>();
    k_hist<<<(NE + 255) / 256, 256>>>(dst);
    k_scan<<<1, 1024>>>();
    k_fill<<<(NE + 255) / 256, 256>>>(src, dst);

    // node aggregation (9)
    k_node<<<NN, 128>>>(out);
}

// round 11
// speedup vs baseline: 1.5562x; 1.0056x over previous
#include <cuda_runtime.h>
#include <cuda_bf16.h>

#define NN 10000
#define NE 640000
#define C 128
#define NH 8
#define HD 16
#define BD 32
#define NEG_SLOPE 0.01f
#define TILE_E 64

// ---------------- packed f32x2 helpers (FFMA2 — only reachable via PTX) ----
#define FMA_F32X2(d, a, b, c) \
    asm("fma.rn.f32x2 %0, %1, %2, %3;" : "=l"(d) : "l"(a), "l"(b), "l"(c))

__device__ __forceinline__ unsigned long long pack2(float lo, float hi) {
    unsigned long long r;
    asm("mov.b64 %0, {%1, %2};" : "=l"(r) : "f"(lo), "f"(hi));
    return r;
}
__device__ __forceinline__ void unpack2(unsigned long long v, float& lo, float& hi) {
    asm("mov.b64 {%0, %1}, %2;" : "=f"(lo), "=f"(hi) : "l"(v));
}

// ---------------- scratch (device globals; no allocation allowed) ----------
__device__ float g_Q[NN * C];
__device__ float g_K[NN * C];
__device__ float g_V[NN * C];
__device__ int   g_cnt[NN];
__device__ int   g_off[NN + 1];
__device__ int   g_cur[NN];
__device__ int2  g_slot[NE];          // {edge, src}
__device__ float g_ex[NE * NH];       // indexed by RAW edge id

// ---------------- node projection GEMM: Out[M,128] = A[M,128] @ W[128,128] -
__global__ __launch_bounds__(256) void k_gemm128(
        const float* __restrict__ A, const float* __restrict__ W,
        float* __restrict__ Out, int M) {
    __shared__ __align__(16) float2 sA2[64][32];   // duplicated (v,v) -> 16KB
    __shared__ __align__(16) float  sW[32][C];     // 16KB
    int tid = threadIdx.x;
    int tx = tid & 31;       // column group (4 cols each)
    int ty = tid >> 5;       // row group (8 rows each)
    int row0 = blockIdx.x * 64;

    unsigned long long acc[8][2];
#pragma unroll
    for (int i = 0; i < 8; i++) { acc[i][0] = 0ull; acc[i][1] = 0ull; }

    for (int kt = 0; kt < C; kt += 32) {
        for (int i = tid; i < 64 * 32; i += 256) {
            int r = i >> 5, k = i & 31;
            float a = (row0 + r < M) ? A[(row0 + r) * C + kt + k] : 0.0f;
            sA2[r][k] = make_float2(a, a);
        }
        for (int i = tid; i < 32 * C; i += 256) {
            int k = i >> 7, c = i & 127;
            sW[k][c] = W[(kt + k) * C + c];
        }
        __syncthreads();
#pragma unroll
        for (int kk = 0; kk < 32; kk++) {
            ulonglong2 b2 = *(const ulonglong2*)&sW[kk][tx * 4];
#pragma unroll
            for (int i = 0; i < 8; i++) {
                unsigned long long aa = *(const unsigned long long*)&sA2[ty * 8 + i][kk];
                FMA_F32X2(acc[i][0], aa, b2.x, acc[i][0]);
                FMA_F32X2(acc[i][1], aa, b2.y, acc[i][1]);
            }
        }
        __syncthreads();
    }
#pragma unroll
    for (int i = 0; i < 8; i++) {
        int r = row0 + ty * 8 + i;
        if (r < M) {
            float4 o;
            unpack2(acc[i][0], o.x, o.y);
            unpack2(acc[i][1], o.z, o.w);
            *(float4*)&Out[r * C + tx * 4] = o;
        }
    }
}

// ---------------- edge pass: tiled GEMM + logits + exp ---------------------
// Tile = 64 edges x 128 channels per 256-thread block.
// Thread = 8 edges (ty) x 4 channels (tx). W_E in smem shared across the 8
// edges; edge coeffs broadcast (all lanes same addr). ~80 regs -> high occ.
__global__ __launch_bounds__(256) void k_edge(
        const float* __restrict__ edge_attrs,
        const int*   __restrict__ esrc,
        const int*   __restrict__ edst,
        const float* __restrict__ W_E,
        const float* __restrict__ att) {
    __shared__ __align__(16) float  sWE[BD][C];       // 16KB, loaded once
    __shared__ __align__(16) float2 sEA[TILE_E][BD];  // 16KB, per tile (dup v,v)
    __shared__ int2 sIdx[TILE_E];                     // {src, dst}

    int tid = threadIdx.x;
    int tx  = tid & 31;      // channel group (4 channels: tx*4..tx*4+3)
    int ty  = tid >> 5;      // edge group (8 edges) == warp id

    for (int i = tid; i < BD * C; i += 256) sWE[i >> 7][i & 127] = W_E[i];
    float4 a = ((const float4*)att)[tx];   // this lane's 4 att coeffs

    const int NT = NE / TILE_E;   // 10000 tiles
    for (int tile = blockIdx.x; tile < NT; tile += gridDim.x) {
        long long e0 = (long long)tile * TILE_E;
        __syncthreads();
        // stage coefficients (sequential edge_attrs) + indices
        for (int i = tid; i < TILE_E * BD; i += 256) {
            float v = edge_attrs[e0 * BD + i];
            sEA[i >> 5][i & 31] = make_float2(v, v);
        }
        if (tid < TILE_E) sIdx[tid] = make_int2(esrc[e0 + tid], edst[e0 + tid]);
        __syncthreads();

        // ---- phase 1: E-projection GEMM (8 edges x 4 channels / thread) ----
        unsigned long long acc[8][2];
#pragma unroll
        for (int e = 0; e < 8; e++) { acc[e][0] = 0ull; acc[e][1] = 0ull; }
#pragma unroll 4
        for (int k = 0; k < BD; k++) {
            ulonglong2 w = *(const ulonglong2*)&sWE[k][tx * 4];
#pragma unroll
            for (int e = 0; e < 8; e++) {
                unsigned long long cf = *(const unsigned long long*)&sEA[ty * 8 + e][k];
                FMA_F32X2(acc[e][0], cf, w.x, acc[e][0]);
                FMA_F32X2(acc[e][1], cf, w.y, acc[e][1]);
            }
        }

        // ---- phase 2: gather Q/K, leaky-relu, logits, exp (prefetch-1) ----
        int2 id = sIdx[ty * 8];
        float4 q = ((const float4*)g_Q)[id.y * 32 + tx];
        float4 k4 = ((const float4*)g_K)[id.x * 32 + tx];
#pragma unroll
        for (int e = 0; e < 8; e++) {
            float4 qn, kn;
            if (e < 7) {
                int2 idn = sIdx[ty * 8 + e + 1];
                qn = ((const float4*)g_Q)[idn.y * 32 + tx];
                kn = ((const float4*)g_K)[idn.x * 32 + tx];
            }
            float ex_, ey, ez, ew;
            unpack2(acc[e][0], ex_, ey);
            unpack2(acc[e][1], ez, ew);
            float sx = ex_ + q.x + k4.x;
            float sy = ey  + q.y + k4.y;
            float sz = ez  + q.z + k4.z;
            float sw = ew  + q.w + k4.w;
            sx = fmaxf(sx, 0.f) + NEG_SLOPE * fminf(sx, 0.f);
            sy = fmaxf(sy, 0.f) + NEG_SLOPE * fminf(sy, 0.f);
            sz = fmaxf(sz, 0.f) + NEG_SLOPE * fminf(sz, 0.f);
            sw = fmaxf(sw, 0.f) + NEG_SLOPE * fminf(sw, 0.f);
            float p = sx * a.x + sy * a.y + sz * a.z + sw * a.w;
            p += __shfl_xor_sync(0xffffffffu, p, 1);
            p += __shfl_xor_sync(0xffffffffu, p, 2);
            if ((tx & 3) == 0) {
                g_ex[(e0 + ty * 8 + e) * NH + (tx >> 2)] = __expf(p);
            }
            q = qn; k4 = kn;
        }
    }
}

// ---------------- CSR build ------------------------------------------------
__global__ void k_zero_cnt() {
    int i = blockIdx.x * blockDim.x + threadIdx.x;
    if (i < NN) g_cnt[i] = 0;
}

__global__ void k_hist(const int* __restrict__ dst) {
    int i = blockIdx.x * blockDim.x + threadIdx.x;
    if (i < NE) atomicAdd(&g_cnt[dst[i]], 1);
}

__global__ void k_scan() {
    __shared__ int warp_tot[32];
    __shared__ int carry_s;
    int tid = threadIdx.x, lane = tid & 31, wid = tid >> 5;
    if (tid == 0) carry_s = 0;
    __syncthreads();
    for (int base = 0; base < NN; base += 1024) {
        int idx = base + tid;
        int v = (idx < NN) ? g_cnt[idx] : 0;
        int x = v;
#pragma unroll
        for (int of = 1; of < 32; of <<= 1) {
            int t = __shfl_up_sync(0xffffffffu, x, of);
            if (lane >= of) x += t;
        }
        if (lane == 31) warp_tot[wid] = x;
        __syncthreads();
        if (wid == 0) {
            int w = warp_tot[lane];
#pragma unroll
            for (int of = 1; of < 32; of <<= 1) {
                int t = __shfl_up_sync(0xffffffffu, w, of);
                if (lane >= of) w += t;
            }
            warp_tot[lane] = w;
        }
        __syncthreads();
        int incl = x + ((wid > 0) ? warp_tot[wid - 1] : 0);
        int excl = carry_s + incl - v;
        if (idx < NN) { g_off[idx] = excl; g_cur[idx] = excl; }
        int tot = warp_tot[31];
        __syncthreads();
        if (tid == 0) carry_s += tot;
        __syncthreads();
    }
    if (threadIdx.x == 0) g_off[NN] = NE;
}

__global__ void k_fill(const int* __restrict__ src, const int* __restrict__ dst) {
    int i = blockIdx.x * blockDim.x + threadIdx.x;
    if (i < NE) {
        int d = dst[i];
        int s = src[i];
        int pos = atomicAdd(&g_cur[d], 1);
        g_slot[pos] = make_int2(i, s);
    }
}

// ---------------- per-node softmax-normalize + weighted aggregate ----------
#define NCHUNK 64
__global__ __launch_bounds__(128) void k_node(float* __restrict__ out) {
    int v = blockIdx.x;
    int tid = threadIdx.x;
    int s0 = g_off[v];
    int s1 = g_off[v + 1];

    __shared__ int2  sSlot[NCHUNK];
    __shared__ float sEx[NCHUNK * NH];
    __shared__ float sden[NH];
    __shared__ float rden[NH];
    if (tid < NH) sden[tid] = 0.0f;

    int h = tid >> 4;        // head of this output channel
    int hh = tid & 7;        // head this thread accumulates denominator for
    float d = 0.0f;
    float acc = 0.0f;

    for (int c = s0; c < s1; c += NCHUNK) {
        int n = min(NCHUNK, s1 - c);
        __syncthreads();
        if (tid < n) sSlot[tid] = g_slot[c + tid];
        __syncthreads();
        for (int i = tid; i < n * NH; i += 128) {
            int jj = i >> 3;
            sEx[i] = g_ex[(long long)sSlot[jj].x * NH + (i & 7)];
        }
        __syncthreads();

        for (int i = tid; i < n * NH; i += 128) d += sEx[i];

        int j = 0;
        for (; j + 3 < n; j += 4) {
            float w0 = sEx[(j + 0) * NH + h];
            float w1 = sEx[(j + 1) * NH + h];
            float w2 = sEx[(j + 2) * NH + h];
            float w3 = sEx[(j + 3) * NH + h];
            float v0 = g_V[sSlot[j + 0].y * C + tid];
            float v1 = g_V[sSlot[j + 1].y * C + tid];
            float v2 = g_V[sSlot[j + 2].y * C + tid];
            float v3 = g_V[sSlot[j + 3].y * C + tid];
            acc += w0 * v0 + w1 * v1 + w2 * v2 + w3 * v3;
        }
        for (; j < n; j++) {
            acc += sEx[j * NH + h] * g_V[sSlot[j].y * C + tid];
        }
    }

    atomicAdd(&sden[hh], d);
    __syncthreads();
    if (tid < NH) rden[tid] = (sden[tid] > 0.0f) ? (1.0f / sden[tid]) : 0.0f;
    __syncthreads();

    out[v * C + tid] = acc * rden[h];
}

// ---------------- launch ---------------------------------------------------
extern "C" void kernel_launch(void* const* d_in, const int* in_sizes, int n_in,
                              void* d_out, int out_size) {
    const float* senders    = (const float*)d_in[0];
    const float* receivers  = (const float*)d_in[1];
    const int*   edge_idx   = (const int*)d_in[2];
    const float* edge_attrs = (const float*)d_in[3];
    const float* W_Q        = (const float*)d_in[4];
    const float* W_K        = (const float*)d_in[5];
    const float* W_V        = (const float*)d_in[6];
    const float* W_E        = (const float*)d_in[7];
    const float* att        = (const float*)d_in[8];
    float* out = (float*)d_out;

    const int* src = edge_idx;
    const int* dst = edge_idx + NE;

    float* dQ; cudaGetSymbolAddress((void**)&dQ, g_Q);
    float* dK; cudaGetSymbolAddress((void**)&dK, g_K);
    float* dV; cudaGetSymbolAddress((void**)&dV, g_V);

    // node projections (1-3)
    int gblocks = (NN + 63) / 64;
    k_gemm128<<<gblocks, 256>>>(receivers, W_Q, dQ, NN);
    k_gemm128<<<gblocks, 256>>>(senders,   W_K, dK, NN);
    k_gemm128<<<gblocks, 256>>>(senders,   W_V, dV, NN);

    // edge pass (4th launch — profiled slot): tiled GEMM formulation
    k_edge<<<1480, 256>>>(edge_attrs, src, dst, W_E, att);

    // CSR build (5-8)
    k_zero_cnt<<<(NN + 255) / 256, 256>>>();
    k_hist<<<(NE + 255) / 256, 256>>>(dst);
    k_scan<<<1, 1024>>>();
    k_fill<<<(NE + 255) / 256, 256>>>(src, dst);

    // node aggregation (9)
    k_node<<<NN, 128>>>(out);
}

// round 12
// speedup vs baseline: 1.5728x; 1.0107x over previous
#include <cuda_runtime.h>
#include <cuda_bf16.h>

#define NN 10000
#define NE 640000
#define C 128
#define NH 8
#define HD 16
#define BD 32
#define NEG_SLOPE 0.01f
#define TILE_E 64

// ---------------- packed f32x2 helpers (FFMA2 — only reachable via PTX) ----
#define FMA_F32X2(d, a, b, c) \
    asm("fma.rn.f32x2 %0, %1, %2, %3;" : "=l"(d) : "l"(a), "l"(b), "l"(c))

__device__ __forceinline__ unsigned long long pack2(float lo, float hi) {
    unsigned long long r;
    asm("mov.b64 %0, {%1, %2};" : "=l"(r) : "f"(lo), "f"(hi));
    return r;
}
__device__ __forceinline__ void unpack2(unsigned long long v, float& lo, float& hi) {
    asm("mov.b64 {%0, %1}, %2;" : "=f"(lo), "=f"(hi) : "l"(v));
}

// ---------------- scratch (device globals; no allocation allowed) ----------
__device__ float g_Q[NN * C];
__device__ float g_K[NN * C];
__device__ float g_V[NN * C];
__device__ int   g_cnt[NN];
__device__ int   g_off[NN + 1];
__device__ int   g_cur[NN];
__device__ int2  g_slot[NE];          // {edge, src}
__device__ float g_ex[NE * NH];       // indexed by RAW edge id

// ---------------- node projection GEMM: Out[M,128] = A[M,128] @ W[128,128] -
__global__ __launch_bounds__(256) void k_gemm128(
        const float* __restrict__ A, const float* __restrict__ W,
        float* __restrict__ Out, int M) {
    __shared__ __align__(16) float2 sA2[64][32];   // duplicated (v,v) -> 16KB
    __shared__ __align__(16) float  sW[32][C];     // 16KB
    int tid = threadIdx.x;
    int tx = tid & 31;       // column group (4 cols each)
    int ty = tid >> 5;       // row group (8 rows each)
    int row0 = blockIdx.x * 64;

    unsigned long long acc[8][2];
#pragma unroll
    for (int i = 0; i < 8; i++) { acc[i][0] = 0ull; acc[i][1] = 0ull; }

    for (int kt = 0; kt < C; kt += 32) {
        for (int i = tid; i < 64 * 32; i += 256) {
            int r = i >> 5, k = i & 31;
            float a = (row0 + r < M) ? A[(row0 + r) * C + kt + k] : 0.0f;
            sA2[r][k] = make_float2(a, a);
        }
        for (int i = tid; i < 32 * C; i += 256) {
            int k = i >> 7, c = i & 127;
            sW[k][c] = W[(kt + k) * C + c];
        }
        __syncthreads();
#pragma unroll
        for (int kk = 0; kk < 32; kk++) {
            ulonglong2 b2 = *(const ulonglong2*)&sW[kk][tx * 4];
#pragma unroll
            for (int i = 0; i < 8; i++) {
                unsigned long long aa = *(const unsigned long long*)&sA2[ty * 8 + i][kk];
                FMA_F32X2(acc[i][0], aa, b2.x, acc[i][0]);
                FMA_F32X2(acc[i][1], aa, b2.y, acc[i][1]);
            }
        }
        __syncthreads();
    }
#pragma unroll
    for (int i = 0; i < 8; i++) {
        int r = row0 + ty * 8 + i;
        if (r < M) {
            float4 o;
            unpack2(acc[i][0], o.x, o.y);
            unpack2(acc[i][1], o.z, o.w);
            *(float4*)&Out[r * C + tx * 4] = o;
        }
    }
}

// ---------------- edge pass: tiled GEMM + logits + exp ---------------------
// Tile = 64 edges x 128 channels per 256-thread block.
// Thread = 8 edges (ty) x 4 channels (tx).
// Coefficients stored k-PAIRED: sEA[e][kp] = (c0,c0,c1,c1) so one LDS.128
// broadcast feeds 4 FFMA2 (halves L1 wavefronts + LDS issue slots).
// min-blocks 3 pushes regs under 86 -> 3 CTAs/SM.
__global__ __launch_bounds__(256, 3) void k_edge(
        const float* __restrict__ edge_attrs,
        const int*   __restrict__ esrc,
        const int*   __restrict__ edst,
        const float* __restrict__ W_E,
        const float* __restrict__ att) {
    __shared__ __align__(16) float  sWE[BD][C];           // 16KB, loaded once
    __shared__ __align__(16) float4 sEA[TILE_E][BD / 2];  // 16KB, (c0,c0,c1,c1)
    __shared__ int2 sIdx[TILE_E];                         // {src, dst}

    int tid = threadIdx.x;
    int tx  = tid & 31;      // channel group (4 channels: tx*4..tx*4+3)
    int ty  = tid >> 5;      // edge group (8 edges) == warp id

    for (int i = tid; i < BD * C; i += 256) sWE[i >> 7][i & 127] = W_E[i];
    float4 a = ((const float4*)att)[tx];   // this lane's 4 att coeffs

    const int NT = NE / TILE_E;   // 10000 tiles
    for (int tile = blockIdx.x; tile < NT; tile += gridDim.x) {
        long long e0 = (long long)tile * TILE_E;
        __syncthreads();
        // stage coefficients k-paired & duplicated; indices
        for (int i = tid; i < TILE_E * (BD / 2); i += 256) {
            int e  = i >> 4;        // edge in tile
            int kp = i & 15;        // k-pair
            float2 c2 = *(const float2*)&edge_attrs[(e0 + e) * BD + 2 * kp];
            sEA[e][kp] = make_float4(c2.x, c2.x, c2.y, c2.y);
        }
        if (tid < TILE_E) sIdx[tid] = make_int2(esrc[e0 + tid], edst[e0 + tid]);
        __syncthreads();

        // ---- phase 1: E-projection GEMM (8 edges x 4 channels / thread) ----
        unsigned long long acc[8][2];
#pragma unroll
        for (int e = 0; e < 8; e++) { acc[e][0] = 0ull; acc[e][1] = 0ull; }
#pragma unroll 4
        for (int kp = 0; kp < BD / 2; kp++) {
            ulonglong2 w0 = *(const ulonglong2*)&sWE[2 * kp][tx * 4];
            ulonglong2 w1 = *(const ulonglong2*)&sWE[2 * kp + 1][tx * 4];
#pragma unroll
            for (int e = 0; e < 8; e++) {
                ulonglong2 cf = *(const ulonglong2*)&sEA[ty * 8 + e][kp];
                FMA_F32X2(acc[e][0], cf.x, w0.x, acc[e][0]);
                FMA_F32X2(acc[e][1], cf.x, w0.y, acc[e][1]);
                FMA_F32X2(acc[e][0], cf.y, w1.x, acc[e][0]);
                FMA_F32X2(acc[e][1], cf.y, w1.y, acc[e][1]);
            }
        }

        // ---- phase 2: gather Q/K, leaky-relu, logits, exp (prefetch-1) ----
        int2 id = sIdx[ty * 8];
        float4 q = ((const float4*)g_Q)[id.y * 32 + tx];
        float4 k4 = ((const float4*)g_K)[id.x * 32 + tx];
#pragma unroll
        for (int e = 0; e < 8; e++) {
            float4 qn, kn;
            if (e < 7) {
                int2 idn = sIdx[ty * 8 + e + 1];
                qn = ((const float4*)g_Q)[idn.y * 32 + tx];
                kn = ((const float4*)g_K)[idn.x * 32 + tx];
            }
            float ex_, ey, ez, ew;
            unpack2(acc[e][0], ex_, ey);
            unpack2(acc[e][1], ez, ew);
            float sx = ex_ + q.x + k4.x;
            float sy = ey  + q.y + k4.y;
            float sz = ez  + q.z + k4.z;
            float sw = ew  + q.w + k4.w;
            sx = fmaxf(sx, 0.f) + NEG_SLOPE * fminf(sx, 0.f);
            sy = fmaxf(sy, 0.f) + NEG_SLOPE * fminf(sy, 0.f);
            sz = fmaxf(sz, 0.f) + NEG_SLOPE * fminf(sz, 0.f);
            sw = fmaxf(sw, 0.f) + NEG_SLOPE * fminf(sw, 0.f);
            float p = sx * a.x + sy * a.y + sz * a.z + sw * a.w;
            p += __shfl_xor_sync(0xffffffffu, p, 1);
            p += __shfl_xor_sync(0xffffffffu, p, 2);
            if ((tx & 3) == 0) {
                g_ex[(e0 + ty * 8 + e) * NH + (tx >> 2)] = __expf(p);
            }
            q = qn; k4 = kn;
        }
    }
}

// ---------------- CSR build ------------------------------------------------
__global__ void k_zero_cnt() {
    int i = blockIdx.x * blockDim.x + threadIdx.x;
    if (i < NN) g_cnt[i] = 0;
}

__global__ void k_hist(const int* __restrict__ dst) {
    int i = blockIdx.x * blockDim.x + threadIdx.x;
    if (i < NE) atomicAdd(&g_cnt[dst[i]], 1);
}

__global__ void k_scan() {
    __shared__ int warp_tot[32];
    __shared__ int carry_s;
    int tid = threadIdx.x, lane = tid & 31, wid = tid >> 5;
    if (tid == 0) carry_s = 0;
    __syncthreads();
    for (int base = 0; base < NN; base += 1024) {
        int idx = base + tid;
        int v = (idx < NN) ? g_cnt[idx] : 0;
        int x = v;
#pragma unroll
        for (int of = 1; of < 32; of <<= 1) {
            int t = __shfl_up_sync(0xffffffffu, x, of);
            if (lane >= of) x += t;
        }
        if (lane == 31) warp_tot[wid] = x;
        __syncthreads();
        if (wid == 0) {
            int w = warp_tot[lane];
#pragma unroll
            for (int of = 1; of < 32; of <<= 1) {
                int t = __shfl_up_sync(0xffffffffu, w, of);
                if (lane >= of) w += t;
            }
            warp_tot[lane] = w;
        }
        __syncthreads();
        int incl = x + ((wid > 0) ? warp_tot[wid - 1] : 0);
        int excl = carry_s + incl - v;
        if (idx < NN) { g_off[idx] = excl; g_cur[idx] = excl; }
        int tot = warp_tot[31];
        __syncthreads();
        if (tid == 0) carry_s += tot;
        __syncthreads();
    }
    if (threadIdx.x == 0) g_off[NN] = NE;
}

__global__ void k_fill(const int* __restrict__ src, const int* __restrict__ dst) {
    int i = blockIdx.x * blockDim.x + threadIdx.x;
    if (i < NE) {
        int d = dst[i];
        int s = src[i];
        int pos = atomicAdd(&g_cur[d], 1);
        g_slot[pos] = make_int2(i, s);
    }
}

// ---------------- per-node softmax-normalize + weighted aggregate ----------
#define NCHUNK 64
__global__ __launch_bounds__(128) void k_node(float* __restrict__ out) {
    int v = blockIdx.x;
    int tid = threadIdx.x;
    int s0 = g_off[v];
    int s1 = g_off[v + 1];

    __shared__ int2  sSlot[NCHUNK];
    __shared__ float sEx[NCHUNK * NH];
    __shared__ float sden[NH];
    __shared__ float rden[NH];
    if (tid < NH) sden[tid] = 0.0f;

    int h = tid >> 4;        // head of this output channel
    int hh = tid & 7;        // head this thread accumulates denominator for
    float d = 0.0f;
    float acc = 0.0f;

    for (int c = s0; c < s1; c += NCHUNK) {
        int n = min(NCHUNK, s1 - c);
        __syncthreads();
        if (tid < n) sSlot[tid] = g_slot[c + tid];
        __syncthreads();
        for (int i = tid; i < n * NH; i += 128) {
            int jj = i >> 3;
            sEx[i] = g_ex[(long long)sSlot[jj].x * NH + (i & 7)];
        }
        __syncthreads();

        for (int i = tid; i < n * NH; i += 128) d += sEx[i];

        int j = 0;
        for (; j + 3 < n; j += 4) {
            float w0 = sEx[(j + 0) * NH + h];
            float w1 = sEx[(j + 1) * NH + h];
            float w2 = sEx[(j + 2) * NH + h];
            float w3 = sEx[(j + 3) * NH + h];
            float v0 = g_V[sSlot[j + 0].y * C + tid];
            float v1 = g_V[sSlot[j + 1].y * C + tid];
            float v2 = g_V[sSlot[j + 2].y * C + tid];
            float v3 = g_V[sSlot[j + 3].y * C + tid];
            acc += w0 * v0 + w1 * v1 + w2 * v2 + w3 * v3;
        }
        for (; j < n; j++) {
            acc += sEx[j * NH + h] * g_V[sSlot[j].y * C + tid];
        }
    }

    atomicAdd(&sden[hh], d);
    __syncthreads();
    if (tid < NH) rden[tid] = (sden[tid] > 0.0f) ? (1.0f / sden[tid]) : 0.0f;
    __syncthreads();

    out[v * C + tid] = acc * rden[h];
}

// ---------------- launch ---------------------------------------------------
extern "C" void kernel_launch(void* const* d_in, const int* in_sizes, int n_in,
                              void* d_out, int out_size) {
    const float* senders    = (const float*)d_in[0];
    const float* receivers  = (const float*)d_in[1];
    const int*   edge_idx   = (const int*)d_in[2];
    const float* edge_attrs = (const float*)d_in[3];
    const float* W_Q        = (const float*)d_in[4];
    const float* W_K        = (const float*)d_in[5];
    const float* W_V        = (const float*)d_in[6];
    const float* W_E        = (const float*)d_in[7];
    const float* att        = (const float*)d_in[8];
    float* out = (float*)d_out;

    const int* src = edge_idx;
    const int* dst = edge_idx + NE;

    float* dQ; cudaGetSymbolAddress((void**)&dQ, g_Q);
    float* dK; cudaGetSymbolAddress((void**)&dK, g_K);
    float* dV; cudaGetSymbolAddress((void**)&dV, g_V);

    // node projections (1-3)
    int gblocks = (NN + 63) / 64;
    k_gemm128<<<gblocks, 256>>>(receivers, W_Q, dQ, NN);
    k_gemm128<<<gblocks, 256>>>(senders,   W_K, dK, NN);
    k_gemm128<<<gblocks, 256>>>(senders,   W_V, dV, NN);

    // edge pass (4th launch — profiled slot): k-paired coefficient GEMM
    k_edge<<<1480, 256>>>(edge_attrs, src, dst, W_E, att);

    // CSR build (5-8)
    k_zero_cnt<<<(NN + 255) / 256, 256>>>();
    k_hist<<<(NE + 255) / 256, 256>>>(dst);
    k_scan<<<1, 1024>>>();
    k_fill<<<(NE + 255) / 256, 256>>>(src, dst);

    // node aggregation (9)
    k_node<<<NN, 128>>>(out);
}

// round 14
// speedup vs baseline: 1.6561x; 1.0530x over previous
#include <cuda_runtime.h>
#include <cuda_bf16.h>

#define NN 10000
#define NE 640000
#define C 128
#define NH 8
#define HD 16
#define BD 32
#define NEG_SLOPE 0.01f
#define TILE_E 128

// ---------------- packed f32x2 helpers (FFMA2 — only reachable via PTX) ----
#define FMA_F32X2(d, a, b, c) \
    asm("fma.rn.f32x2 %0, %1, %2, %3;" : "=l"(d) : "l"(a), "l"(b), "l"(c))

__device__ __forceinline__ unsigned long long pack2(float lo, float hi) {
    unsigned long long r;
    asm("mov.b64 %0, {%1, %2};" : "=l"(r) : "f"(lo), "f"(hi));
    return r;
}
__device__ __forceinline__ void unpack2(unsigned long long v, float& lo, float& hi) {
    asm("mov.b64 {%0, %1}, %2;" : "=f"(lo), "=f"(hi) : "l"(v));
}

// ---------------- scratch (device globals; no allocation allowed) ----------
__device__ float g_Q[NN * C];
__device__ float g_K[NN * C];
__device__ float g_V[NN * C];
__device__ int   g_cnt[NN];
__device__ int   g_off[NN + 1];
__device__ int   g_cur[NN];
__device__ int2  g_slot[NE];          // {edge, src}
__device__ float g_ex[NE * NH];       // indexed by RAW edge id

// ---------------- node projection GEMM: Out[M,128] = A[M,128] @ W[128,128] -
__global__ __launch_bounds__(256) void k_gemm128(
        const float* __restrict__ A, const float* __restrict__ W,
        float* __restrict__ Out, int M) {
    __shared__ __align__(16) float2 sA2[64][32];   // duplicated (v,v) -> 16KB
    __shared__ __align__(16) float  sW[32][C];     // 16KB
    int tid = threadIdx.x;
    int tx = tid & 31;       // column group (4 cols each)
    int ty = tid >> 5;       // row group (8 rows each)
    int row0 = blockIdx.x * 64;

    unsigned long long acc[8][2];
#pragma unroll
    for (int i = 0; i < 8; i++) { acc[i][0] = 0ull; acc[i][1] = 0ull; }

    for (int kt = 0; kt < C; kt += 32) {
        for (int i = tid; i < 64 * 32; i += 256) {
            int r = i >> 5, k = i & 31;
            float a = (row0 + r < M) ? A[(row0 + r) * C + kt + k] : 0.0f;
            sA2[r][k] = make_float2(a, a);
        }
        for (int i = tid; i < 32 * C; i += 256) {
            int k = i >> 7, c = i & 127;
            sW[k][c] = W[(kt + k) * C + c];
        }
        __syncthreads();
#pragma unroll
        for (int kk = 0; kk < 32; kk++) {
            ulonglong2 b2 = *(const ulonglong2*)&sW[kk][tx * 4];
#pragma unroll
            for (int i = 0; i < 8; i++) {
                unsigned long long aa = *(const unsigned long long*)&sA2[ty * 8 + i][kk];
                FMA_F32X2(acc[i][0], aa, b2.x, acc[i][0]);
                FMA_F32X2(acc[i][1], aa, b2.y, acc[i][1]);
            }
        }
        __syncthreads();
    }
#pragma unroll
    for (int i = 0; i < 8; i++) {
        int r = row0 + ty * 8 + i;
        if (r < M) {
            float4 o;
            unpack2(acc[i][0], o.x, o.y);
            unpack2(acc[i][1], o.z, o.w);
            *(float4*)&Out[r * C + tx * 4] = o;
        }
    }
}

// ---------------- edge pass: tiled GEMM + logits + exp ---------------------
// Tile = 128 edges x 128 channels per 256-thread block.
// Thread = 16 edges (ty) x 4 channels (tx).
// cf loaded as raw float4 quads (4 k's per broadcast LDS.128), duplicated to
// f32x2 in registers; W amortized over 16 edges. Cuts smem wavefronts/edge
// ~46 -> ~28 (the measured binding resource).
__global__ __launch_bounds__(256, 2) void k_edge(
        const float* __restrict__ edge_attrs,
        const int*   __restrict__ esrc,
        const int*   __restrict__ edst,
        const float* __restrict__ W_E,
        const float* __restrict__ att) {
    __shared__ __align__(16) float  sWE[BD][C];           // 16KB, loaded once
    __shared__ __align__(16) float4 sEA[TILE_E][BD / 4];  // 16KB, raw quads
    __shared__ int2 sIdx[TILE_E];                         // {src, dst}

    int tid = threadIdx.x;
    int tx  = tid & 31;      // channel group (4 channels: tx*4..tx*4+3)
    int ty  = tid >> 5;      // edge group (16 edges) == warp id

    for (int i = tid; i < BD * C; i += 256) sWE[i >> 7][i & 127] = W_E[i];
    float4 a = ((const float4*)att)[tx];   // this lane's 4 att coeffs

    const int NT = NE / TILE_E;   // 5000 tiles
    for (int tile = blockIdx.x; tile < NT; tile += gridDim.x) {
        long long e0 = (long long)tile * TILE_E;
        __syncthreads();
        // stage coefficients as raw float4 quads (coalesced) + indices
        for (int i = tid; i < TILE_E * (BD / 4); i += 256) {
            sEA[i >> 3][i & 7] = ((const float4*)edge_attrs)[e0 * (BD / 4) + i];
        }
        if (tid < TILE_E) sIdx[tid] = make_int2(esrc[e0 + tid], edst[e0 + tid]);
        __syncthreads();

        // ---- phase 1: E-projection GEMM (16 edges x 4 channels / thread) --
        unsigned long long acc[16][2];
#pragma unroll
        for (int e = 0; e < 16; e++) { acc[e][0] = 0ull; acc[e][1] = 0ull; }
#pragma unroll 1
        for (int kq = 0; kq < BD / 4; kq++) {
            // W for 4 consecutive k's, this thread's 4 channels
            ulonglong2 w0 = *(const ulonglong2*)&sWE[4 * kq + 0][tx * 4];
            ulonglong2 w1 = *(const ulonglong2*)&sWE[4 * kq + 1][tx * 4];
            ulonglong2 w2 = *(const ulonglong2*)&sWE[4 * kq + 2][tx * 4];
            ulonglong2 w3 = *(const ulonglong2*)&sWE[4 * kq + 3][tx * 4];
#pragma unroll
            for (int e = 0; e < 16; e++) {
                float4 cf = sEA[ty * 16 + e][kq];     // broadcast LDS.128
                unsigned long long c0 = pack2(cf.x, cf.x);
                unsigned long long c1 = pack2(cf.y, cf.y);
                unsigned long long c2 = pack2(cf.z, cf.z);
                unsigned long long c3 = pack2(cf.w, cf.w);
                FMA_F32X2(acc[e][0], c0, w0.x, acc[e][0]);
                FMA_F32X2(acc[e][1], c0, w0.y, acc[e][1]);
                FMA_F32X2(acc[e][0], c1, w1.x, acc[e][0]);
                FMA_F32X2(acc[e][1], c1, w1.y, acc[e][1]);
                FMA_F32X2(acc[e][0], c2, w2.x, acc[e][0]);
                FMA_F32X2(acc[e][1], c2, w2.y, acc[e][1]);
                FMA_F32X2(acc[e][0], c3, w3.x, acc[e][0]);
                FMA_F32X2(acc[e][1], c3, w3.y, acc[e][1]);
            }
        }

        // ---- phase 2: gather Q/K, leaky-relu, logits, exp (prefetch-1) ----
        int2 id = sIdx[ty * 16];
        float4 q = ((const float4*)g_Q)[id.y * 32 + tx];
        float4 k4 = ((const float4*)g_K)[id.x * 32 + tx];
#pragma unroll
        for (int e = 0; e < 16; e++) {
            float4 qn, kn;
            if (e < 15) {
                int2 idn = sIdx[ty * 16 + e + 1];
                qn = ((const float4*)g_Q)[idn.y * 32 + tx];
                kn = ((const float4*)g_K)[idn.x * 32 + tx];
            }
            float ex_, ey, ez, ew;
            unpack2(acc[e][0], ex_, ey);
            unpack2(acc[e][1], ez, ew);
            float sx = ex_ + q.x + k4.x;
            float sy = ey  + q.y + k4.y;
            float sz = ez  + q.z + k4.z;
            float sw = ew  + q.w + k4.w;
            sx = fmaxf(sx, 0.f) + NEG_SLOPE * fminf(sx, 0.f);
            sy = fmaxf(sy, 0.f) + NEG_SLOPE * fminf(sy, 0.f);
            sz = fmaxf(sz, 0.f) + NEG_SLOPE * fminf(sz, 0.f);
            sw = fmaxf(sw, 0.f) + NEG_SLOPE * fminf(sw, 0.f);
            float p = sx * a.x + sy * a.y + sz * a.z + sw * a.w;
            p += __shfl_xor_sync(0xffffffffu, p, 1);
            p += __shfl_xor_sync(0xffffffffu, p, 2);
            if ((tx & 3) == 0) {
                g_ex[(e0 + ty * 16 + e) * NH + (tx >> 2)] = __expf(p);
            }
            q = qn; k4 = kn;
        }
    }
}

// ---------------- CSR build ------------------------------------------------
__global__ void k_zero_cnt() {
    int i = blockIdx.x * blockDim.x + threadIdx.x;
    if (i < NN) g_cnt[i] = 0;
}

__global__ void k_hist(const int* __restrict__ dst) {
    int i = blockIdx.x * blockDim.x + threadIdx.x;
    if (i < NE) atomicAdd(&g_cnt[dst[i]], 1);
}

__global__ void k_scan() {
    __shared__ int warp_tot[32];
    __shared__ int carry_s;
    int tid = threadIdx.x, lane = tid & 31, wid = tid >> 5;
    if (tid == 0) carry_s = 0;
    __syncthreads();
    for (int base = 0; base < NN; base += 1024) {
        int idx = base + tid;
        int v = (idx < NN) ? g_cnt[idx] : 0;
        int x = v;
#pragma unroll
        for (int of = 1; of < 32; of <<= 1) {
            int t = __shfl_up_sync(0xffffffffu, x, of);
            if (lane >= of) x += t;
        }
        if (lane == 31) warp_tot[wid] = x;
        __syncthreads();
        if (wid == 0) {
            int w = warp_tot[lane];
#pragma unroll
            for (int of = 1; of < 32; of <<= 1) {
                int t = __shfl_up_sync(0xffffffffu, w, of);
                if (lane >= of) w += t;
            }
            warp_tot[lane] = w;
        }
        __syncthreads();
        int incl = x + ((wid > 0) ? warp_tot[wid - 1] : 0);
        int excl = carry_s + incl - v;
        if (idx < NN) { g_off[idx] = excl; g_cur[idx] = excl; }
        int tot = warp_tot[31];
        __syncthreads();
        if (tid == 0) carry_s += tot;
        __syncthreads();
    }
    if (threadIdx.x == 0) g_off[NN] = NE;
}

__global__ void k_fill(const int* __restrict__ src, const int* __restrict__ dst) {
    int i = blockIdx.x * blockDim.x + threadIdx.x;
    if (i < NE) {
        int d = dst[i];
        int s = src[i];
        int pos = atomicAdd(&g_cur[d], 1);
        g_slot[pos] = make_int2(i, s);
    }
}

// ---------------- per-node softmax-normalize + weighted aggregate ----------
#define NCHUNK 64
__global__ __launch_bounds__(128) void k_node(float* __restrict__ out) {
    int v = blockIdx.x;
    int tid = threadIdx.x;
    int s0 = g_off[v];
    int s1 = g_off[v + 1];

    __shared__ int2  sSlot[NCHUNK];
    __shared__ float sEx[NCHUNK * NH];
    __shared__ float sden[NH];
    __shared__ float rden[NH];
    if (tid < NH) sden[tid] = 0.0f;

    int h = tid >> 4;        // head of this output channel
    int hh = tid & 7;        // head this thread accumulates denominator for
    float d = 0.0f;
    float acc = 0.0f;

    for (int c = s0; c < s1; c += NCHUNK) {
        int n = min(NCHUNK, s1 - c);
        __syncthreads();
        if (tid < n) sSlot[tid] = g_slot[c + tid];
        __syncthreads();
        for (int i = tid; i < n * NH; i += 128) {
            int jj = i >> 3;
            sEx[i] = g_ex[(long long)sSlot[jj].x * NH + (i & 7)];
        }
        __syncthreads();

        for (int i = tid; i < n * NH; i += 128) d += sEx[i];

        int j = 0;
        for (; j + 3 < n; j += 4) {
            float w0 = sEx[(j + 0) * NH + h];
            float w1 = sEx[(j + 1) * NH + h];
            float w2 = sEx[(j + 2) * NH + h];
            float w3 = sEx[(j + 3) * NH + h];
            float v0 = g_V[sSlot[j + 0].y * C + tid];
            float v1 = g_V[sSlot[j + 1].y * C + tid];
            float v2 = g_V[sSlot[j + 2].y * C + tid];
            float v3 = g_V[sSlot[j + 3].y * C + tid];
            acc += w0 * v0 + w1 * v1 + w2 * v2 + w3 * v3;
        }
        for (; j < n; j++) {
            acc += sEx[j * NH + h] * g_V[sSlot[j].y * C + tid];
        }
    }

    atomicAdd(&sden[hh], d);
    __syncthreads();
    if (tid < NH) rden[tid] = (sden[tid] > 0.0f) ? (1.0f / sden[tid]) : 0.0f;
    __syncthreads();

    out[v * C + tid] = acc * rden[h];
}

// ---------------- launch ---------------------------------------------------
extern "C" void kernel_launch(void* const* d_in, const int* in_sizes, int n_in,
                              void* d_out, int out_size) {
    const float* senders    = (const float*)d_in[0];
    const float* receivers  = (const float*)d_in[1];
    const int*   edge_idx   = (const int*)d_in[2];
    const float* edge_attrs = (const float*)d_in[3];
    const float* W_Q        = (const float*)d_in[4];
    const float* W_K        = (const float*)d_in[5];
    const float* W_V        = (const float*)d_in[6];
    const float* W_E        = (const float*)d_in[7];
    const float* att        = (const float*)d_in[8];
    float* out = (float*)d_out;

    const int* src = edge_idx;
    const int* dst = edge_idx + NE;

    float* dQ; cudaGetSymbolAddress((void**)&dQ, g_Q);
    float* dK; cudaGetSymbolAddress((void**)&dK, g_K);
    float* dV; cudaGetSymbolAddress((void**)&dV, g_V);

    // node projections (1-3)
    int gblocks = (NN + 63) / 64;
    k_gemm128<<<gblocks, 256>>>(receivers, W_Q, dQ, NN);
    k_gemm128<<<gblocks, 256>>>(senders,   W_K, dK, NN);
    k_gemm128<<<gblocks, 256>>>(senders,   W_V, dV, NN);

    // edge pass (4th launch — profiled slot): quad-packed coefficient GEMM
    k_edge<<<1480, 256>>>(edge_attrs, src, dst, W_E, att);

    // CSR build (5-8)
    k_zero_cnt<<<(NN + 255) / 256, 256>>>();
    k_hist<<<(NE + 255) / 256, 256>>>(dst);
    k_scan<<<1, 1024>>>();
    k_fill<<<(NE + 255) / 256, 256>>>(src, dst);

    // node aggregation (9)
    k_node<<<NN, 128>>>(out);
}